// round 5
// baseline (speedup 1.0000x reference)
#include <cuda_runtime.h>
#include <cuda_bf16.h>
#include <math.h>
#include <stdint.h>

// Problem dims
#define T_DIM 4096
#define B_DIM 8
#define C_DIM 1024
#define F_DIM 128
#define NPROJ 6
#define N6 (NPROJ * F_DIM)          // 768
#define M_DIM (T_DIM * B_DIM)       // 32768
#define G_GRP 32                    // row groups per batch for scan
#define R_ROWS (F_DIM / G_GRP)      // 4 rows per warp
#define PFD 4                       // scan prefetch depth

#define INV_SQRT_F 0.08838834764831845f  // 1/sqrt(128)

// ---------------------------------------------------------------------------
// Scratch (static device arrays: allocation-free per harness rules)
// ---------------------------------------------------------------------------
__device__ float d_W6[(size_t)N6 * C_DIM];                       // 3 MB packed weights
__device__ float d_b6[N6];                                       // packed biases
__device__ float d_P[(size_t)M_DIM * N6];                        // 96 MB projections
__device__ float d_opart[(size_t)M_DIM * G_GRP * F_DIM];         // 512 MB partial outputs
__device__ float d_o[(size_t)M_DIM * F_DIM];                     // 16 MB reduced o

// ---------------------------------------------------------------------------
// K0: pack the 6 projection weights/biases (slot order A,B,C,D,I,S)
// ---------------------------------------------------------------------------
__global__ void pack_weights_kernel(
    const float* __restrict__ Aw, const float* __restrict__ Bw,
    const float* __restrict__ Cw, const float* __restrict__ Dw,
    const float* __restrict__ Iw, const float* __restrict__ Sw,
    const float* __restrict__ Ab, const float* __restrict__ Bb,
    const float* __restrict__ Cb, const float* __restrict__ Db,
    const float* __restrict__ Ib, const float* __restrict__ Sb)
{
    const int per = F_DIM * C_DIM;
    int i = blockIdx.x * blockDim.x + threadIdx.x;
    if (i < per) {
        d_W6[0 * per + i] = Aw[i];
        d_W6[1 * per + i] = Bw[i];
        d_W6[2 * per + i] = Cw[i];
        d_W6[3 * per + i] = Dw[i];
        d_W6[4 * per + i] = Iw[i];
        d_W6[5 * per + i] = Sw[i];
    }
    if (i < F_DIM) {
        d_b6[0 * F_DIM + i] = Ab[i];
        d_b6[1 * F_DIM + i] = Bb[i];
        d_b6[2 * F_DIM + i] = Cb[i];
        d_b6[3 * F_DIM + i] = Db[i];
        d_b6[4 * F_DIM + i] = Ib[i];
        d_b6[5 * F_DIM + i] = Sb[i];
    }
}

// ---------------------------------------------------------------------------
// K1/K4: 3xBF16 GEMM via ldmatrix + mma.m16n8k16 (NT):
//   C[m,n] = sum_k A[m,k]*B[n,k] (+bias[n])
// BM=BN=128, BK=32. 256 threads = 8 warps (4 M x 2 N), warp tile 32x64.
// fp32 split into bf16 hi/lo during SMEM store; passes hi*hi + hi*lo + lo*hi.
// SMEM row stride 40 bf16 (80B): conflict-free for ldmatrix 8-row phases.
// Requires M%128==0, N%128==0, K%32==0.
// ---------------------------------------------------------------------------
#define ASTRIDE 40   // bf16 elements per SMEM row (80 bytes)

__device__ __forceinline__ void cvt_split(float4 v, uint2& h, uint2& l) {
    __nv_bfloat16 hx = __float2bfloat16_rn(v.x);
    __nv_bfloat16 hy = __float2bfloat16_rn(v.y);
    __nv_bfloat16 hz = __float2bfloat16_rn(v.z);
    __nv_bfloat16 hw = __float2bfloat16_rn(v.w);
    float rx = v.x - __bfloat162float(hx);
    float ry = v.y - __bfloat162float(hy);
    float rz = v.z - __bfloat162float(hz);
    float rw = v.w - __bfloat162float(hw);
    h.x = (uint32_t)__bfloat16_as_ushort(hx) | ((uint32_t)__bfloat16_as_ushort(hy) << 16);
    h.y = (uint32_t)__bfloat16_as_ushort(hz) | ((uint32_t)__bfloat16_as_ushort(hw) << 16);
    __nv_bfloat16 lx = __float2bfloat16_rn(rx);
    __nv_bfloat16 ly = __float2bfloat16_rn(ry);
    __nv_bfloat16 lz = __float2bfloat16_rn(rz);
    __nv_bfloat16 lw = __float2bfloat16_rn(rw);
    l.x = (uint32_t)__bfloat16_as_ushort(lx) | ((uint32_t)__bfloat16_as_ushort(ly) << 16);
    l.y = (uint32_t)__bfloat16_as_ushort(lz) | ((uint32_t)__bfloat16_as_ushort(lw) << 16);
}

__device__ __forceinline__ void ldm_x4(uint32_t (&r)[4], const __nv_bfloat16* p) {
    uint32_t addr = (uint32_t)__cvta_generic_to_shared(p);
    asm volatile("ldmatrix.sync.aligned.m8n8.x4.shared.b16 {%0,%1,%2,%3}, [%4];"
                 : "=r"(r[0]), "=r"(r[1]), "=r"(r[2]), "=r"(r[3]) : "r"(addr));
}

__device__ __forceinline__ void mma_bf16(float* d, const uint32_t* a,
                                         uint32_t b0, uint32_t b1) {
    asm volatile(
        "mma.sync.aligned.m16n8k16.row.col.f32.bf16.bf16.f32 "
        "{%0,%1,%2,%3}, {%4,%5,%6,%7}, {%8,%9}, {%0,%1,%2,%3};"
        : "+f"(d[0]), "+f"(d[1]), "+f"(d[2]), "+f"(d[3])
        : "r"(a[0]), "r"(a[1]), "r"(a[2]), "r"(a[3]), "r"(b0), "r"(b1));
}

__global__ void __launch_bounds__(256, 2)
bf16_gemm_kernel(const float* __restrict__ A, const float* __restrict__ B,
                 const float* __restrict__ bias, float* __restrict__ C,
                 int M, int N, int K)
{
    __shared__ __align__(16) __nv_bfloat16 Ah[128 * ASTRIDE];
    __shared__ __align__(16) __nv_bfloat16 Al[128 * ASTRIDE];
    __shared__ __align__(16) __nv_bfloat16 Bh[128 * ASTRIDE];
    __shared__ __align__(16) __nv_bfloat16 Bl[128 * ASTRIDE];

    const int tid = threadIdx.x;
    const int wid = tid >> 5;
    const int lane = tid & 31;
    const int grp = lane >> 2;
    const int tig = lane & 3;

    const int bm = blockIdx.y * 128;
    const int bn = blockIdx.x * 128;
    const int warp_m = (wid >> 1) * 32;
    const int warp_n = (wid & 1) * 64;

    float acc[2][8][4];
#pragma unroll
    for (int mt = 0; mt < 2; mt++)
#pragma unroll
        for (int nt = 0; nt < 8; nt++)
#pragma unroll
            for (int q = 0; q < 4; q++) acc[mt][nt][q] = 0.0f;

    const int lrow = tid >> 1;          // 0..127
    const int koff = (tid & 1) * 16;    // 0 or 16

    // precomputed ldmatrix element offsets for this lane
    const int a_e0 = (warp_m + (lane & 15)) * ASTRIDE + ((lane >> 4) & 1) * 8;
    const int b_e0 = (warp_n + (lane & 7) + ((lane >> 4) & 1) * 8) * ASTRIDE
                   + ((lane >> 3) & 1) * 8;

    for (int k0 = 0; k0 < K; k0 += 32) {
        // loader: each thread handles one row, 16 consecutive k floats
        {
            const float* ap = A + (size_t)(bm + lrow) * K + k0 + koff;
            float4 v0 = *(const float4*)(ap);
            float4 v1 = *(const float4*)(ap + 4);
            float4 v2 = *(const float4*)(ap + 8);
            float4 v3 = *(const float4*)(ap + 12);
            uint2 h0, l0, h1, l1, h2, l2, h3, l3;
            cvt_split(v0, h0, l0); cvt_split(v1, h1, l1);
            cvt_split(v2, h2, l2); cvt_split(v3, h3, l3);
            int so = lrow * ASTRIDE + koff;
            *(uint4*)(Ah + so)     = make_uint4(h0.x, h0.y, h1.x, h1.y);
            *(uint4*)(Ah + so + 8) = make_uint4(h2.x, h2.y, h3.x, h3.y);
            *(uint4*)(Al + so)     = make_uint4(l0.x, l0.y, l1.x, l1.y);
            *(uint4*)(Al + so + 8) = make_uint4(l2.x, l2.y, l3.x, l3.y);

            const float* bp = B + (size_t)(bn + lrow) * K + k0 + koff;
            v0 = *(const float4*)(bp);
            v1 = *(const float4*)(bp + 4);
            v2 = *(const float4*)(bp + 8);
            v3 = *(const float4*)(bp + 12);
            cvt_split(v0, h0, l0); cvt_split(v1, h1, l1);
            cvt_split(v2, h2, l2); cvt_split(v3, h3, l3);
            *(uint4*)(Bh + so)     = make_uint4(h0.x, h0.y, h1.x, h1.y);
            *(uint4*)(Bh + so + 8) = make_uint4(h2.x, h2.y, h3.x, h3.y);
            *(uint4*)(Bl + so)     = make_uint4(l0.x, l0.y, l1.x, l1.y);
            *(uint4*)(Bl + so + 8) = make_uint4(l2.x, l2.y, l3.x, l3.y);
        }
        __syncthreads();

#pragma unroll
        for (int ks = 0; ks < 2; ks++) {
            uint32_t afh[2][4], afl[2][4];
#pragma unroll
            for (int mt = 0; mt < 2; mt++) {
                int e = a_e0 + mt * 16 * ASTRIDE + ks * 16;
                ldm_x4(afh[mt], Ah + e);
                ldm_x4(afl[mt], Al + e);
            }
            uint32_t bfh[4][4], bfl[4][4];
#pragma unroll
            for (int ntp = 0; ntp < 4; ntp++) {
                int e = b_e0 + ntp * 16 * ASTRIDE + ks * 16;
                ldm_x4(bfh[ntp], Bh + e);
                ldm_x4(bfl[ntp], Bl + e);
            }
#pragma unroll
            for (int mt = 0; mt < 2; mt++)
#pragma unroll
                for (int nt = 0; nt < 8; nt++) {
                    const int ntp = nt >> 1;
                    const int s = (nt & 1) * 2;
                    mma_bf16(acc[mt][nt], afh[mt], bfh[ntp][s], bfh[ntp][s + 1]);
                    mma_bf16(acc[mt][nt], afh[mt], bfl[ntp][s], bfl[ntp][s + 1]);
                    mma_bf16(acc[mt][nt], afl[mt], bfh[ntp][s], bfh[ntp][s + 1]);
                }
        }
        __syncthreads();
    }

    // epilogue: c0,c1 at (row, 2*tig), c2,c3 at (row+8, 2*tig)
#pragma unroll
    for (int mt = 0; mt < 2; mt++) {
        int r0 = bm + warp_m + mt * 16 + grp;
#pragma unroll
        for (int nt = 0; nt < 8; nt++) {
            int col = bn + warp_n + nt * 8 + 2 * tig;
            float b0 = 0.f, b1 = 0.f;
            if (bias != nullptr) { b0 = bias[col]; b1 = bias[col + 1]; }
            float2 v0 = make_float2(acc[mt][nt][0] + b0, acc[mt][nt][1] + b1);
            float2 v1 = make_float2(acc[mt][nt][2] + b0, acc[mt][nt][3] + b1);
            *(float2*)(C + (size_t)r0 * N + col) = v0;
            *(float2*)(C + (size_t)(r0 + 8) * N + col) = v1;
        }
    }
}

// ---------------------------------------------------------------------------
// K2: sequential scan. Grid (G_GRP, B_DIM), 32 threads per CTA.
// Lane l owns 4 CONSECUTIVE columns [4l, 4l+4). Depth-PFD register prefetch
// ring; sigmoid + 1/sqrt(F) scaling applied at load time (off critical path).
// ---------------------------------------------------------------------------
__device__ __forceinline__ float warp_allsum(float x) {
#pragma unroll
    for (int o = 16; o >= 1; o >>= 1)
        x += __shfl_xor_sync(0xffffffffu, x, o);
    return x;
}

__global__ void __launch_bounds__(32)
scan_kernel(const float* __restrict__ P, const float* __restrict__ state_in,
            float* __restrict__ opart, float* __restrict__ state_out)
{
    const int g = blockIdx.x;
    const int b = blockIdx.y;
    const int l = threadIdx.x;
    const int rowbase = g * R_ROWS;

    // state: lane holds float4 per owned row (columns 4l..4l+3)
    float4 st[R_ROWS];
    {
        const float* sb = state_in + ((size_t)b * F_DIM + rowbase) * F_DIM + 4 * l;
#pragma unroll
        for (int r = 0; r < R_ROWS; r++)
            st[r] = *(const float4*)(sb + r * F_DIM);
    }

    // prefetch ring
    float4 pa[PFD], pb[PFD], pd[PFD], pg[PFD];
    float pc[PFD][R_ROWS], ps[PFD][R_ROWS];

#define LOADSTAGE(slot, tt) do {                                              \
    const float* _p = P + (size_t)((size_t)(tt) * B_DIM + b) * N6;            \
    float4 _a = *(const float4*)(_p + 0 * F_DIM + 4 * l);                     \
    float4 _b = *(const float4*)(_p + 1 * F_DIM + 4 * l);                     \
    float4 _d = *(const float4*)(_p + 3 * F_DIM + 4 * l);                     \
    float4 _i = *(const float4*)(_p + 4 * F_DIM + 4 * l);                     \
    pa[slot] = _a;                                                            \
    pb[slot] = make_float4(_b.x * INV_SQRT_F, _b.y * INV_SQRT_F,              \
                           _b.z * INV_SQRT_F, _b.w * INV_SQRT_F);             \
    pd[slot] = _d;                                                            \
    pg[slot] = make_float4(1.0f / (1.0f + __expf(-_i.x)),                     \
                           1.0f / (1.0f + __expf(-_i.y)),                     \
                           1.0f / (1.0f + __expf(-_i.z)),                     \
                           1.0f / (1.0f + __expf(-_i.w)));                    \
    _Pragma("unroll")                                                         \
    for (int _r = 0; _r < R_ROWS; _r++) {                                     \
        pc[slot][_r] = __ldg(_p + 2 * F_DIM + rowbase + _r);                  \
        ps[slot][_r] = __ldg(_p + 5 * F_DIM + rowbase + _r);                  \
    }                                                                         \
} while (0)

#pragma unroll
    for (int s = 0; s < PFD; s++) LOADSTAGE(s, s);

#pragma unroll 1
    for (int t0 = 0; t0 < T_DIM; t0 += PFD) {
#pragma unroll
        for (int ph = 0; ph < PFD; ph++) {
            const int t = t0 + ph;

            const float4 a = pa[ph];
            const float4 bb = pb[ph];
            const float4 dd = pd[ph];
            const float4 gg = pg[ph];

            // v[r] = row r of old state dot a (tree + butterfly)
            float v[R_ROWS];
#pragma unroll
            for (int r = 0; r < R_ROWS; r++) {
                float m01 = fmaf(st[r].y, a.y, st[r].x * a.x);
                float m23 = fmaf(st[r].w, a.w, st[r].z * a.z);
                v[r] = m01 + m23;
            }
#pragma unroll
            for (int r = 0; r < R_ROWS; r++) v[r] = warp_allsum(v[r]);

            // st = st*g + v*b + c*d
#pragma unroll
            for (int r = 0; r < R_ROWS; r++) {
                const float cr = pc[ph][r];
                st[r].x = fmaf(st[r].x, gg.x, fmaf(v[r], bb.x, cr * dd.x));
                st[r].y = fmaf(st[r].y, gg.y, fmaf(v[r], bb.y, cr * dd.y));
                st[r].z = fmaf(st[r].z, gg.z, fmaf(v[r], bb.z, cr * dd.z));
                st[r].w = fmaf(st[r].w, gg.w, fmaf(v[r], bb.w, cr * dd.w));
            }

            // partial output over owned rows
            float4 po = make_float4(0.f, 0.f, 0.f, 0.f);
#pragma unroll
            for (int r = 0; r < R_ROWS; r++) {
                const float sr = ps[ph][r];
                po.x = fmaf(sr, st[r].x, po.x);
                po.y = fmaf(sr, st[r].y, po.y);
                po.z = fmaf(sr, st[r].z, po.z);
                po.w = fmaf(sr, st[r].w, po.w);
            }
            float* ob = opart +
                ((size_t)((size_t)t * B_DIM + b) * G_GRP + g) * F_DIM + 4 * l;
            *(float4*)ob = po;

            // refill this slot with step t+PFD
            if (t + PFD < T_DIM) LOADSTAGE(ph, t + PFD);
        }
    }

    float* so = state_out + ((size_t)b * F_DIM + rowbase) * F_DIM + 4 * l;
#pragma unroll
    for (int r = 0; r < R_ROWS; r++)
        *(float4*)(so + r * F_DIM) = st[r];
#undef LOADSTAGE
}

// ---------------------------------------------------------------------------
// K3: reduce partial outputs over G
// ---------------------------------------------------------------------------
__global__ void reduce_opart_kernel(const float* __restrict__ opart,
                                    float* __restrict__ o)
{
    const int F4 = F_DIM / 4;
    size_t idx = (size_t)blockIdx.x * blockDim.x + threadIdx.x;
    size_t total = (size_t)M_DIM * F4;
    if (idx >= total) return;
    size_t row = idx / F4;
    int f4 = (int)(idx % F4);
    const float4* src = (const float4*)opart + row * (size_t)(G_GRP * F4) + f4;
    float4 acc = make_float4(0.f, 0.f, 0.f, 0.f);
#pragma unroll
    for (int gg = 0; gg < G_GRP; gg++) {
        float4 xv = src[(size_t)gg * F4];
        acc.x += xv.x; acc.y += xv.y; acc.z += xv.z; acc.w += xv.w;
    }
    ((float4*)o)[idx] = acc;
}

// ---------------------------------------------------------------------------
// launch
// ---------------------------------------------------------------------------
extern "C" void kernel_launch(void* const* d_in, const int* in_sizes, int n_in,
                              void* d_out, int out_size)
{
    const float* x     = (const float*)d_in[0];
    const float* state = (const float*)d_in[1];
    const float* A_w = (const float*)d_in[2];
    const float* A_b = (const float*)d_in[3];
    const float* B_w = (const float*)d_in[4];
    const float* B_b = (const float*)d_in[5];
    const float* C_w = (const float*)d_in[6];
    const float* C_b = (const float*)d_in[7];
    const float* D_w = (const float*)d_in[8];
    const float* D_b = (const float*)d_in[9];
    const float* I_w = (const float*)d_in[10];
    const float* I_b = (const float*)d_in[11];
    const float* S_w = (const float*)d_in[12];
    const float* S_b = (const float*)d_in[13];
    const float* O_w = (const float*)d_in[14];

    float* out = (float*)d_out;

    float *W6, *b6, *P, *opart, *o;
    cudaGetSymbolAddress((void**)&W6, d_W6);
    cudaGetSymbolAddress((void**)&b6, d_b6);
    cudaGetSymbolAddress((void**)&P, d_P);
    cudaGetSymbolAddress((void**)&opart, d_opart);
    cudaGetSymbolAddress((void**)&o, d_o);

    const size_t y_elems = (size_t)M_DIM * C_DIM;
    const size_t st_elems = (size_t)B_DIM * F_DIM * F_DIM;
    float* y = out;
    float* state_out =
        ((size_t)out_size >= y_elems + st_elems) ? (out + y_elems) : o;

    // K0: pack weights
    pack_weights_kernel<<<(F_DIM * C_DIM + 255) / 256, 256>>>(
        A_w, B_w, C_w, D_w, I_w, S_w, A_b, B_b, C_b, D_b, I_b, S_b);

    // K1: P = x @ W6^T + b6   (M=32768, N=768, K=1024) via 3xBF16 mma.sync
    {
        dim3 grid(N6 / 128, M_DIM / 128);
        bf16_gemm_kernel<<<grid, 256>>>(x, W6, b6, P, M_DIM, N6, C_DIM);
    }

    // K2: scan
    {
        dim3 grid(G_GRP, B_DIM);
        scan_kernel<<<grid, 32>>>(P, state, opart, state_out);
    }

    // K3: reduce partials
    {
        size_t total = (size_t)M_DIM * (F_DIM / 4);
        reduce_opart_kernel<<<(unsigned)((total + 255) / 256), 256>>>(opart, o);
    }

    // K4: y = o @ O_w^T   (M=32768, N=1024, K=128) via 3xBF16 mma.sync
    {
        dim3 grid(C_DIM / 128, M_DIM / 128);
        bf16_gemm_kernel<<<grid, 256>>>(o, O_w, nullptr, y, M_DIM, C_DIM, F_DIM);
    }
}

// round 6
// speedup vs baseline: 2.0719x; 2.0719x over previous
#include <cuda_runtime.h>
#include <cuda_bf16.h>
#include <math.h>
#include <stdint.h>

// Problem dims
#define T_DIM 4096
#define B_DIM 8
#define C_DIM 1024
#define F_DIM 128
#define NPROJ 6
#define N6 (NPROJ * F_DIM)          // 768
#define M_DIM (T_DIM * B_DIM)       // 32768
#define G_GRP 32                    // row groups per batch for scan
#define R_ROWS (F_DIM / G_GRP)      // 4 rows per warp
#define PFD 4                       // scan prefetch depth

#define INV_SQRT_F 0.08838834764831845f  // 1/sqrt(128)

// ---------------------------------------------------------------------------
// Scratch (static device arrays: allocation-free per harness rules)
// ---------------------------------------------------------------------------
__device__ float d_W6[(size_t)N6 * C_DIM];                       // 3 MB packed weights
__device__ float d_b6[N6];                                       // packed biases
__device__ float d_P[(size_t)M_DIM * N6];                        // 96 MB projections
__device__ float d_opart[(size_t)M_DIM * G_GRP * F_DIM];         // 512 MB partial outputs
__device__ float d_o[(size_t)M_DIM * F_DIM];                     // 16 MB reduced o

// ---------------------------------------------------------------------------
// dummy kernel: shifts the ncu -s 5 capture slot onto the scan kernel
// ---------------------------------------------------------------------------
__global__ void noop_kernel() {}

// ---------------------------------------------------------------------------
// K0: pack the 6 projection weights/biases (slot order A,B,C,D,I,S)
// ---------------------------------------------------------------------------
__global__ void pack_weights_kernel(
    const float* __restrict__ Aw, const float* __restrict__ Bw,
    const float* __restrict__ Cw, const float* __restrict__ Dw,
    const float* __restrict__ Iw, const float* __restrict__ Sw,
    const float* __restrict__ Ab, const float* __restrict__ Bb,
    const float* __restrict__ Cb, const float* __restrict__ Db,
    const float* __restrict__ Ib, const float* __restrict__ Sb)
{
    const int per = F_DIM * C_DIM;
    int i = blockIdx.x * blockDim.x + threadIdx.x;
    if (i < per) {
        d_W6[0 * per + i] = Aw[i];
        d_W6[1 * per + i] = Bw[i];
        d_W6[2 * per + i] = Cw[i];
        d_W6[3 * per + i] = Dw[i];
        d_W6[4 * per + i] = Iw[i];
        d_W6[5 * per + i] = Sw[i];
    }
    if (i < F_DIM) {
        d_b6[0 * F_DIM + i] = Ab[i];
        d_b6[1 * F_DIM + i] = Bb[i];
        d_b6[2 * F_DIM + i] = Cb[i];
        d_b6[3 * F_DIM + i] = Db[i];
        d_b6[4 * F_DIM + i] = Ib[i];
        d_b6[5 * F_DIM + i] = Sb[i];
    }
}

// ---------------------------------------------------------------------------
// K1/K4: 3xBF16 GEMM via ldmatrix + mma.m16n8k16 (NT):
//   C[m,n] = sum_k A[m,k]*B[n,k] (+bias[n])
// BM=BN=128, BK=32. 256 threads = 8 warps (4 M x 2 N), warp tile 32x64.
// fp32 split into bf16 hi/lo during SMEM store; passes hi*hi + hi*lo + lo*hi.
// B-fragments are TRANSIENT (one ntp pair live at a time) so the kernel fits
// the 128-reg cap of minBlocksPerMultiprocessor=2 without spilling.
// SMEM row stride 40 bf16 (80B): conflict-free for ldmatrix 8-row phases.
// ---------------------------------------------------------------------------
#define ASTRIDE 40   // bf16 elements per SMEM row (80 bytes)

__device__ __forceinline__ void cvt_split(float4 v, uint2& h, uint2& l) {
    __nv_bfloat16 hx = __float2bfloat16_rn(v.x);
    __nv_bfloat16 hy = __float2bfloat16_rn(v.y);
    __nv_bfloat16 hz = __float2bfloat16_rn(v.z);
    __nv_bfloat16 hw = __float2bfloat16_rn(v.w);
    float rx = v.x - __bfloat162float(hx);
    float ry = v.y - __bfloat162float(hy);
    float rz = v.z - __bfloat162float(hz);
    float rw = v.w - __bfloat162float(hw);
    h.x = (uint32_t)__bfloat16_as_ushort(hx) | ((uint32_t)__bfloat16_as_ushort(hy) << 16);
    h.y = (uint32_t)__bfloat16_as_ushort(hz) | ((uint32_t)__bfloat16_as_ushort(hw) << 16);
    __nv_bfloat16 lx = __float2bfloat16_rn(rx);
    __nv_bfloat16 ly = __float2bfloat16_rn(ry);
    __nv_bfloat16 lz = __float2bfloat16_rn(rz);
    __nv_bfloat16 lw = __float2bfloat16_rn(rw);
    l.x = (uint32_t)__bfloat16_as_ushort(lx) | ((uint32_t)__bfloat16_as_ushort(ly) << 16);
    l.y = (uint32_t)__bfloat16_as_ushort(lz) | ((uint32_t)__bfloat16_as_ushort(lw) << 16);
}

__device__ __forceinline__ void ldm_x4(uint32_t (&r)[4], const __nv_bfloat16* p) {
    uint32_t addr = (uint32_t)__cvta_generic_to_shared(p);
    asm volatile("ldmatrix.sync.aligned.m8n8.x4.shared.b16 {%0,%1,%2,%3}, [%4];"
                 : "=r"(r[0]), "=r"(r[1]), "=r"(r[2]), "=r"(r[3]) : "r"(addr));
}

__device__ __forceinline__ void mma_bf16(float* d, const uint32_t* a,
                                         uint32_t b0, uint32_t b1) {
    asm volatile(
        "mma.sync.aligned.m16n8k16.row.col.f32.bf16.bf16.f32 "
        "{%0,%1,%2,%3}, {%4,%5,%6,%7}, {%8,%9}, {%0,%1,%2,%3};"
        : "+f"(d[0]), "+f"(d[1]), "+f"(d[2]), "+f"(d[3])
        : "r"(a[0]), "r"(a[1]), "r"(a[2]), "r"(a[3]), "r"(b0), "r"(b1));
}

__global__ void __launch_bounds__(256, 2)
bf16_gemm_kernel(const float* __restrict__ A, const float* __restrict__ B,
                 const float* __restrict__ bias, float* __restrict__ C,
                 int M, int N, int K)
{
    __shared__ __align__(16) __nv_bfloat16 Ah[128 * ASTRIDE];
    __shared__ __align__(16) __nv_bfloat16 Al[128 * ASTRIDE];
    __shared__ __align__(16) __nv_bfloat16 Bh[128 * ASTRIDE];
    __shared__ __align__(16) __nv_bfloat16 Bl[128 * ASTRIDE];

    const int tid = threadIdx.x;
    const int wid = tid >> 5;
    const int lane = tid & 31;
    const int grp = lane >> 2;
    const int tig = lane & 3;

    const int bm = blockIdx.y * 128;
    const int bn = blockIdx.x * 128;
    const int warp_m = (wid >> 1) * 32;
    const int warp_n = (wid & 1) * 64;

    float acc[2][8][4];
#pragma unroll
    for (int mt = 0; mt < 2; mt++)
#pragma unroll
        for (int nt = 0; nt < 8; nt++)
#pragma unroll
            for (int q = 0; q < 4; q++) acc[mt][nt][q] = 0.0f;

    const int lrow = tid >> 1;          // 0..127
    const int koff = (tid & 1) * 16;    // 0 or 16

    // ldmatrix element offsets for this lane
    const int a_e0 = (warp_m + (lane & 15)) * ASTRIDE + ((lane >> 4) & 1) * 8;
    const int b_e0 = (warp_n + (lane & 7) + ((lane >> 4) & 1) * 8) * ASTRIDE
                   + ((lane >> 3) & 1) * 8;

    for (int k0 = 0; k0 < K; k0 += 32) {
        // loader: each thread handles one row, 16 consecutive k floats
        {
            const float* ap = A + (size_t)(bm + lrow) * K + k0 + koff;
            float4 v0 = *(const float4*)(ap);
            float4 v1 = *(const float4*)(ap + 4);
            float4 v2 = *(const float4*)(ap + 8);
            float4 v3 = *(const float4*)(ap + 12);
            uint2 h0, l0, h1, l1, h2, l2, h3, l3;
            cvt_split(v0, h0, l0); cvt_split(v1, h1, l1);
            cvt_split(v2, h2, l2); cvt_split(v3, h3, l3);
            int so = lrow * ASTRIDE + koff;
            *(uint4*)(Ah + so)     = make_uint4(h0.x, h0.y, h1.x, h1.y);
            *(uint4*)(Ah + so + 8) = make_uint4(h2.x, h2.y, h3.x, h3.y);
            *(uint4*)(Al + so)     = make_uint4(l0.x, l0.y, l1.x, l1.y);
            *(uint4*)(Al + so + 8) = make_uint4(l2.x, l2.y, l3.x, l3.y);

            const float* bp = B + (size_t)(bn + lrow) * K + k0 + koff;
            v0 = *(const float4*)(bp);
            v1 = *(const float4*)(bp + 4);
            v2 = *(const float4*)(bp + 8);
            v3 = *(const float4*)(bp + 12);
            cvt_split(v0, h0, l0); cvt_split(v1, h1, l1);
            cvt_split(v2, h2, l2); cvt_split(v3, h3, l3);
            *(uint4*)(Bh + so)     = make_uint4(h0.x, h0.y, h1.x, h1.y);
            *(uint4*)(Bh + so + 8) = make_uint4(h2.x, h2.y, h3.x, h3.y);
            *(uint4*)(Bl + so)     = make_uint4(l0.x, l0.y, l1.x, l1.y);
            *(uint4*)(Bl + so + 8) = make_uint4(l2.x, l2.y, l3.x, l3.y);
        }
        __syncthreads();

#pragma unroll
        for (int ks = 0; ks < 2; ks++) {
            uint32_t afh[2][4], afl[2][4];
#pragma unroll
            for (int mt = 0; mt < 2; mt++) {
                int e = a_e0 + mt * 16 * ASTRIDE + ks * 16;
                ldm_x4(afh[mt], Ah + e);
                ldm_x4(afl[mt], Al + e);
            }
#pragma unroll
            for (int ntp = 0; ntp < 4; ntp++) {
                // transient B fragments: only 8 regs live at a time
                uint32_t bh[4], bl[4];
                int e = b_e0 + ntp * 16 * ASTRIDE + ks * 16;
                ldm_x4(bh, Bh + e);
                ldm_x4(bl, Bl + e);
#pragma unroll
                for (int mt = 0; mt < 2; mt++) {
                    mma_bf16(acc[mt][2 * ntp],     afh[mt], bh[0], bh[1]);
                    mma_bf16(acc[mt][2 * ntp],     afh[mt], bl[0], bl[1]);
                    mma_bf16(acc[mt][2 * ntp],     afl[mt], bh[0], bh[1]);
                    mma_bf16(acc[mt][2 * ntp + 1], afh[mt], bh[2], bh[3]);
                    mma_bf16(acc[mt][2 * ntp + 1], afh[mt], bl[2], bl[3]);
                    mma_bf16(acc[mt][2 * ntp + 1], afl[mt], bh[2], bh[3]);
                }
            }
        }
        __syncthreads();
    }

    // epilogue: c0,c1 at (row, 2*tig), c2,c3 at (row+8, 2*tig)
#pragma unroll
    for (int mt = 0; mt < 2; mt++) {
        int r0 = bm + warp_m + mt * 16 + grp;
#pragma unroll
        for (int nt = 0; nt < 8; nt++) {
            int col = bn + warp_n + nt * 8 + 2 * tig;
            float b0 = 0.f, b1 = 0.f;
            if (bias != nullptr) { b0 = bias[col]; b1 = bias[col + 1]; }
            float2 v0 = make_float2(acc[mt][nt][0] + b0, acc[mt][nt][1] + b1);
            float2 v1 = make_float2(acc[mt][nt][2] + b0, acc[mt][nt][3] + b1);
            *(float2*)(C + (size_t)r0 * N + col) = v0;
            *(float2*)(C + (size_t)(r0 + 8) * N + col) = v1;
        }
    }
}

// ---------------------------------------------------------------------------
// K2: sequential scan. Grid (G_GRP, B_DIM), 32 threads per CTA.
// Lane l owns 4 CONSECUTIVE columns [4l, 4l+4). Depth-PFD register prefetch
// ring; sigmoid + 1/sqrt(F) scaling applied at load time (off critical path).
// ---------------------------------------------------------------------------
__device__ __forceinline__ float warp_allsum(float x) {
#pragma unroll
    for (int o = 16; o >= 1; o >>= 1)
        x += __shfl_xor_sync(0xffffffffu, x, o);
    return x;
}

__global__ void __launch_bounds__(32)
scan_kernel(const float* __restrict__ P, const float* __restrict__ state_in,
            float* __restrict__ opart, float* __restrict__ state_out)
{
    const int g = blockIdx.x;
    const int b = blockIdx.y;
    const int l = threadIdx.x;
    const int rowbase = g * R_ROWS;

    // state: lane holds float4 per owned row (columns 4l..4l+3)
    float4 st[R_ROWS];
    {
        const float* sb = state_in + ((size_t)b * F_DIM + rowbase) * F_DIM + 4 * l;
#pragma unroll
        for (int r = 0; r < R_ROWS; r++)
            st[r] = *(const float4*)(sb + r * F_DIM);
    }

    // prefetch ring
    float4 pa[PFD], pb[PFD], pd[PFD], pg[PFD];
    float pc[PFD][R_ROWS], ps[PFD][R_ROWS];

#define LOADSTAGE(slot, tt) do {                                              \
    const float* _p = P + (size_t)((size_t)(tt) * B_DIM + b) * N6;            \
    float4 _a = *(const float4*)(_p + 0 * F_DIM + 4 * l);                     \
    float4 _b = *(const float4*)(_p + 1 * F_DIM + 4 * l);                     \
    float4 _d = *(const float4*)(_p + 3 * F_DIM + 4 * l);                     \
    float4 _i = *(const float4*)(_p + 4 * F_DIM + 4 * l);                     \
    pa[slot] = _a;                                                            \
    pb[slot] = make_float4(_b.x * INV_SQRT_F, _b.y * INV_SQRT_F,              \
                           _b.z * INV_SQRT_F, _b.w * INV_SQRT_F);             \
    pd[slot] = _d;                                                            \
    pg[slot] = make_float4(1.0f / (1.0f + __expf(-_i.x)),                     \
                           1.0f / (1.0f + __expf(-_i.y)),                     \
                           1.0f / (1.0f + __expf(-_i.z)),                     \
                           1.0f / (1.0f + __expf(-_i.w)));                    \
    _Pragma("unroll")                                                         \
    for (int _r = 0; _r < R_ROWS; _r++) {                                     \
        pc[slot][_r] = __ldg(_p + 2 * F_DIM + rowbase + _r);                  \
        ps[slot][_r] = __ldg(_p + 5 * F_DIM + rowbase + _r);                  \
    }                                                                         \
} while (0)

#pragma unroll
    for (int s = 0; s < PFD; s++) LOADSTAGE(s, s);

#pragma unroll 1
    for (int t0 = 0; t0 < T_DIM; t0 += PFD) {
#pragma unroll
        for (int ph = 0; ph < PFD; ph++) {
            const int t = t0 + ph;

            const float4 a = pa[ph];
            const float4 bb = pb[ph];
            const float4 dd = pd[ph];
            const float4 gg = pg[ph];

            // v[r] = row r of old state dot a (tree + butterfly)
            float v[R_ROWS];
#pragma unroll
            for (int r = 0; r < R_ROWS; r++) {
                float m01 = fmaf(st[r].y, a.y, st[r].x * a.x);
                float m23 = fmaf(st[r].w, a.w, st[r].z * a.z);
                v[r] = m01 + m23;
            }
#pragma unroll
            for (int r = 0; r < R_ROWS; r++) v[r] = warp_allsum(v[r]);

            // st = st*g + v*b + c*d
#pragma unroll
            for (int r = 0; r < R_ROWS; r++) {
                const float cr = pc[ph][r];
                st[r].x = fmaf(st[r].x, gg.x, fmaf(v[r], bb.x, cr * dd.x));
                st[r].y = fmaf(st[r].y, gg.y, fmaf(v[r], bb.y, cr * dd.y));
                st[r].z = fmaf(st[r].z, gg.z, fmaf(v[r], bb.z, cr * dd.z));
                st[r].w = fmaf(st[r].w, gg.w, fmaf(v[r], bb.w, cr * dd.w));
            }

            // partial output over owned rows
            float4 po = make_float4(0.f, 0.f, 0.f, 0.f);
#pragma unroll
            for (int r = 0; r < R_ROWS; r++) {
                const float sr = ps[ph][r];
                po.x = fmaf(sr, st[r].x, po.x);
                po.y = fmaf(sr, st[r].y, po.y);
                po.z = fmaf(sr, st[r].z, po.z);
                po.w = fmaf(sr, st[r].w, po.w);
            }
            float* ob = opart +
                ((size_t)((size_t)t * B_DIM + b) * G_GRP + g) * F_DIM + 4 * l;
            *(float4*)ob = po;

            // branch-free clamped refill of this slot with step t+PFD
            {
                int tload = t + PFD;
                if (tload > T_DIM - 1) tload = T_DIM - 1;
                LOADSTAGE(ph, tload);
            }
        }
    }

    float* so = state_out + ((size_t)b * F_DIM + rowbase) * F_DIM + 4 * l;
#pragma unroll
    for (int r = 0; r < R_ROWS; r++)
        *(float4*)(so + r * F_DIM) = st[r];
#undef LOADSTAGE
}

// ---------------------------------------------------------------------------
// K3: reduce partial outputs over G
// ---------------------------------------------------------------------------
__global__ void reduce_opart_kernel(const float* __restrict__ opart,
                                    float* __restrict__ o)
{
    const int F4 = F_DIM / 4;
    size_t idx = (size_t)blockIdx.x * blockDim.x + threadIdx.x;
    size_t total = (size_t)M_DIM * F4;
    if (idx >= total) return;
    size_t row = idx / F4;
    int f4 = (int)(idx % F4);
    const float4* src = (const float4*)opart + row * (size_t)(G_GRP * F4) + f4;
    float4 acc = make_float4(0.f, 0.f, 0.f, 0.f);
#pragma unroll
    for (int gg = 0; gg < G_GRP; gg++) {
        float4 xv = src[(size_t)gg * F4];
        acc.x += xv.x; acc.y += xv.y; acc.z += xv.z; acc.w += xv.w;
    }
    ((float4*)o)[idx] = acc;
}

// ---------------------------------------------------------------------------
// launch
// ---------------------------------------------------------------------------
extern "C" void kernel_launch(void* const* d_in, const int* in_sizes, int n_in,
                              void* d_out, int out_size)
{
    const float* x     = (const float*)d_in[0];
    const float* state = (const float*)d_in[1];
    const float* A_w = (const float*)d_in[2];
    const float* A_b = (const float*)d_in[3];
    const float* B_w = (const float*)d_in[4];
    const float* B_b = (const float*)d_in[5];
    const float* C_w = (const float*)d_in[6];
    const float* C_b = (const float*)d_in[7];
    const float* D_w = (const float*)d_in[8];
    const float* D_b = (const float*)d_in[9];
    const float* I_w = (const float*)d_in[10];
    const float* I_b = (const float*)d_in[11];
    const float* S_w = (const float*)d_in[12];
    const float* S_b = (const float*)d_in[13];
    const float* O_w = (const float*)d_in[14];

    float* out = (float*)d_out;

    float *W6, *b6, *P, *opart, *o;
    cudaGetSymbolAddress((void**)&W6, d_W6);
    cudaGetSymbolAddress((void**)&b6, d_b6);
    cudaGetSymbolAddress((void**)&P, d_P);
    cudaGetSymbolAddress((void**)&opart, d_opart);
    cudaGetSymbolAddress((void**)&o, d_o);

    const size_t y_elems = (size_t)M_DIM * C_DIM;
    const size_t st_elems = (size_t)B_DIM * F_DIM * F_DIM;
    float* y = out;
    float* state_out =
        ((size_t)out_size >= y_elems + st_elems) ? (out + y_elems) : o;

    // K0: pack weights
    pack_weights_kernel<<<(F_DIM * C_DIM + 255) / 256, 256>>>(
        A_w, B_w, C_w, D_w, I_w, S_w, A_b, B_b, C_b, D_b, I_b, S_b);

    // stream-slot shifter: moves the ncu capture slot from K3 onto K2 (scan)
    noop_kernel<<<1, 1>>>();

    // K1: P = x @ W6^T + b6   (M=32768, N=768, K=1024) via 3xBF16 mma.sync
    {
        dim3 grid(N6 / 128, M_DIM / 128);
        bf16_gemm_kernel<<<grid, 256>>>(x, W6, b6, P, M_DIM, N6, C_DIM);
    }

    // K2: scan
    {
        dim3 grid(G_GRP, B_DIM);
        scan_kernel<<<grid, 32>>>(P, state, opart, state_out);
    }

    // K3: reduce partials
    {
        size_t total = (size_t)M_DIM * (F_DIM / 4);
        reduce_opart_kernel<<<(unsigned)((total + 255) / 256), 256>>>(opart, o);
    }

    // K4: y = o @ O_w^T   (M=32768, N=1024, K=128) via 3xBF16 mma.sync
    {
        dim3 grid(C_DIM / 128, M_DIM / 128);
        bf16_gemm_kernel<<<grid, 256>>>(o, O_w, nullptr, y, M_DIM, C_DIM, F_DIM);
    }
}

// round 7
// speedup vs baseline: 2.1506x; 1.0380x over previous
#include <cuda_runtime.h>
#include <cuda_bf16.h>
#include <math.h>
#include <stdint.h>

// Problem dims
#define T_DIM 4096
#define B_DIM 8
#define C_DIM 1024
#define F_DIM 128
#define NPROJ 6
#define N6 (NPROJ * F_DIM)          // 768
#define M_DIM (T_DIM * B_DIM)       // 32768
#define G_GRP 32                    // row groups per batch for scan
#define R_ROWS (F_DIM / G_GRP)      // 4 rows per warp
#define PFD 4                       // scan prefetch depth

#define INV_SQRT_F 0.08838834764831845f  // 1/sqrt(128)

// ---------------------------------------------------------------------------
// Scratch (static device arrays: allocation-free per harness rules)
// ---------------------------------------------------------------------------
__device__ float d_b6[N6];                                            // packed biases
__device__ float d_P[(size_t)M_DIM * N6];                             // 96 MB projections
__device__ float d_opart[(size_t)M_DIM * G_GRP * F_DIM];              // 512 MB partials
__device__ float d_stfb[(size_t)B_DIM * F_DIM * F_DIM];               // state fallback
__device__ __nv_bfloat16 d_xh[(size_t)M_DIM * C_DIM];                 // 64 MB x hi
__device__ __nv_bfloat16 d_xl[(size_t)M_DIM * C_DIM];                 // 64 MB x lo
__device__ __nv_bfloat16 d_W6h[(size_t)N6 * C_DIM];                   // 1.5 MB
__device__ __nv_bfloat16 d_W6l[(size_t)N6 * C_DIM];                   // 1.5 MB
__device__ __nv_bfloat16 d_Owh[(size_t)C_DIM * F_DIM];
__device__ __nv_bfloat16 d_Owl[(size_t)C_DIM * F_DIM];
__device__ __nv_bfloat16 d_oh[(size_t)M_DIM * F_DIM];                 // 8 MB
__device__ __nv_bfloat16 d_ol[(size_t)M_DIM * F_DIM];                 // 8 MB

// ---------------------------------------------------------------------------
// helpers
// ---------------------------------------------------------------------------
__device__ __forceinline__ void split1(float v, __nv_bfloat16& h, __nv_bfloat16& l) {
    h = __float2bfloat16_rn(v);
    l = __float2bfloat16_rn(v - __bfloat162float(h));
}

// dummy kernel: keeps K1 at ncu capture position 4
__global__ void noop_kernel() {}

// ---------------------------------------------------------------------------
// K0: pack biases + split all weights into bf16 hi/lo
// ---------------------------------------------------------------------------
__global__ void pack_weights_kernel(
    const float* __restrict__ Aw, const float* __restrict__ Bw,
    const float* __restrict__ Cw, const float* __restrict__ Dw,
    const float* __restrict__ Iw, const float* __restrict__ Sw,
    const float* __restrict__ Ab, const float* __restrict__ Bb,
    const float* __restrict__ Cb, const float* __restrict__ Db,
    const float* __restrict__ Ib, const float* __restrict__ Sb,
    const float* __restrict__ Ow)
{
    const int per = F_DIM * C_DIM;  // 131072
    int i = blockIdx.x * blockDim.x + threadIdx.x;
    if (i < per) {
        split1(Aw[i], d_W6h[0 * per + i], d_W6l[0 * per + i]);
        split1(Bw[i], d_W6h[1 * per + i], d_W6l[1 * per + i]);
        split1(Cw[i], d_W6h[2 * per + i], d_W6l[2 * per + i]);
        split1(Dw[i], d_W6h[3 * per + i], d_W6l[3 * per + i]);
        split1(Iw[i], d_W6h[4 * per + i], d_W6l[4 * per + i]);
        split1(Sw[i], d_W6h[5 * per + i], d_W6l[5 * per + i]);
        split1(Ow[i], d_Owh[i], d_Owl[i]);
    }
    if (i < F_DIM) {
        d_b6[0 * F_DIM + i] = Ab[i];
        d_b6[1 * F_DIM + i] = Bb[i];
        d_b6[2 * F_DIM + i] = Cb[i];
        d_b6[3 * F_DIM + i] = Db[i];
        d_b6[4 * F_DIM + i] = Ib[i];
        d_b6[5 * F_DIM + i] = Sb[i];
    }
}

// ---------------------------------------------------------------------------
// K0b: split x into bf16 hi/lo
// ---------------------------------------------------------------------------
__global__ void split_x_kernel(const float* __restrict__ in)
{
    size_t i4 = (size_t)blockIdx.x * blockDim.x + threadIdx.x;
    size_t total4 = (size_t)M_DIM * C_DIM / 4;
    if (i4 >= total4) return;
    float4 v = ((const float4*)in)[i4];
    __nv_bfloat16 h0, l0, h1, l1, h2, l2, h3, l3;
    split1(v.x, h0, l0); split1(v.y, h1, l1);
    split1(v.z, h2, l2); split1(v.w, h3, l3);
    uint2 ph, pl;
    ph.x = (uint32_t)__bfloat16_as_ushort(h0) | ((uint32_t)__bfloat16_as_ushort(h1) << 16);
    ph.y = (uint32_t)__bfloat16_as_ushort(h2) | ((uint32_t)__bfloat16_as_ushort(h3) << 16);
    pl.x = (uint32_t)__bfloat16_as_ushort(l0) | ((uint32_t)__bfloat16_as_ushort(l1) << 16);
    pl.y = (uint32_t)__bfloat16_as_ushort(l2) | ((uint32_t)__bfloat16_as_ushort(l3) << 16);
    ((uint2*)d_xh)[i4] = ph;
    ((uint2*)d_xl)[i4] = pl;
}

// ---------------------------------------------------------------------------
// K1/K4: 3xBF16 GEMM, cp.async 2-stage pipeline + ldmatrix + mma.m16n8k16 (NT)
//   C[m,n] = sum_k A[m,k]*B[n,k] (+bias[n]);  A,B pre-split bf16 hi/lo.
// BM=BN=128, BK=32. 256 threads = 8 warps (4 M x 2 N), warp tile 32x64.
// SMEM: 2 stages x 4 mats x 128 rows x ASTRIDE(40) bf16 (80B padded rows,
// conflict-free for ldmatrix). 80 KB dynamic.
// ---------------------------------------------------------------------------
#define ASTRIDE 40
#define TILE_E (128 * ASTRIDE)          // elements per matrix tile
#define TILE_B (TILE_E * 2)             // bytes per matrix tile (10240)
#define STAGE_B (4 * TILE_B)            // bytes per stage (40960)
#define GEMM_SMEM (2 * STAGE_B)         // 81920

__device__ __forceinline__ void ldm_x4(uint32_t (&r)[4], const __nv_bfloat16* p) {
    uint32_t addr = (uint32_t)__cvta_generic_to_shared(p);
    asm volatile("ldmatrix.sync.aligned.m8n8.x4.shared.b16 {%0,%1,%2,%3}, [%4];"
                 : "=r"(r[0]), "=r"(r[1]), "=r"(r[2]), "=r"(r[3]) : "r"(addr));
}

__device__ __forceinline__ void mma_bf16(float* d, const uint32_t* a,
                                         uint32_t b0, uint32_t b1) {
    asm volatile(
        "mma.sync.aligned.m16n8k16.row.col.f32.bf16.bf16.f32 "
        "{%0,%1,%2,%3}, {%4,%5,%6,%7}, {%8,%9}, {%0,%1,%2,%3};"
        : "+f"(d[0]), "+f"(d[1]), "+f"(d[2]), "+f"(d[3])
        : "r"(a[0]), "r"(a[1]), "r"(a[2]), "r"(a[3]), "r"(b0), "r"(b1));
}

__device__ __forceinline__ void cp16(uint32_t dst, const void* src) {
    asm volatile("cp.async.ca.shared.global [%0], [%1], 16;"
                 :: "r"(dst), "l"(src));
}

__global__ void __launch_bounds__(256, 2)
bf16_gemm_async(const __nv_bfloat16* __restrict__ Ah,
                const __nv_bfloat16* __restrict__ Al,
                const __nv_bfloat16* __restrict__ Bh,
                const __nv_bfloat16* __restrict__ Bl,
                const float* __restrict__ bias, float* __restrict__ C,
                int M, int N, int K)
{
    extern __shared__ __align__(16) __nv_bfloat16 smd[];

    const int tid = threadIdx.x;
    const int wid = tid >> 5;
    const int lane = tid & 31;
    const int grp = lane >> 2;
    const int tig = lane & 3;

    const int bm = blockIdx.y * 128;
    const int bn = blockIdx.x * 128;
    const int warp_m = (wid >> 1) * 32;
    const int warp_n = (wid & 1) * 64;

    float acc[2][8][4];
#pragma unroll
    for (int mt = 0; mt < 2; mt++)
#pragma unroll
        for (int nt = 0; nt < 8; nt++)
#pragma unroll
            for (int q = 0; q < 4; q++) acc[mt][nt][q] = 0.0f;

    // loader mapping: thread -> (row, 2 chunks of 16B) per matrix
    const int lrow = tid >> 1;          // 0..127
    const int cb = (tid & 1) * 2;       // chunk base 0 or 2 (chunks of 8 bf16)

    const __nv_bfloat16* gsrc[4];
    gsrc[0] = Ah + (size_t)(bm + lrow) * K;
    gsrc[1] = Al + (size_t)(bm + lrow) * K;
    gsrc[2] = Bh + (size_t)(bn + lrow) * K;
    gsrc[3] = Bl + (size_t)(bn + lrow) * K;

    const uint32_t smem_base = (uint32_t)__cvta_generic_to_shared(smd);
    const uint32_t dst0 = smem_base + (uint32_t)(lrow * ASTRIDE * 2 + cb * 16);

    // ldmatrix element offsets (within one matrix tile)
    const int a_e0 = (warp_m + (lane & 15)) * ASTRIDE + ((lane >> 4) & 1) * 8;
    const int b_e0 = (warp_n + (lane & 7) + ((lane >> 4) & 1) * 8) * ASTRIDE
                   + ((lane >> 3) & 1) * 8;

#define ISSUE_STAGE(stg, kk) do {                                          \
    uint32_t _d = dst0 + (uint32_t)(stg) * STAGE_B;                        \
    _Pragma("unroll")                                                      \
    for (int _m = 0; _m < 4; _m++) {                                       \
        cp16(_d + (cb + 0) * 0 + 0, gsrc[_m] + (kk) + (cb + 0) * 8);       \
        cp16(_d + 16,              gsrc[_m] + (kk) + (cb + 1) * 8);        \
        _d += TILE_B;                                                      \
    }                                                                      \
    asm volatile("cp.async.commit_group;");                                \
} while (0)

    const int niter = K >> 5;
    ISSUE_STAGE(0, 0);

    for (int i = 0; i < niter; i++) {
        if (i + 1 < niter) {
            ISSUE_STAGE((i + 1) & 1, (i + 1) * 32);
            asm volatile("cp.async.wait_group 1;");
        } else {
            asm volatile("cp.async.wait_group 0;");
        }
        __syncthreads();

        const __nv_bfloat16* sAh = smd + (size_t)((i & 1) * 4 + 0) * TILE_E;
        const __nv_bfloat16* sAl = smd + (size_t)((i & 1) * 4 + 1) * TILE_E;
        const __nv_bfloat16* sBh = smd + (size_t)((i & 1) * 4 + 2) * TILE_E;
        const __nv_bfloat16* sBl = smd + (size_t)((i & 1) * 4 + 3) * TILE_E;

#pragma unroll
        for (int ks = 0; ks < 2; ks++) {
            uint32_t afh[2][4], afl[2][4];
#pragma unroll
            for (int mt = 0; mt < 2; mt++) {
                int e = a_e0 + mt * 16 * ASTRIDE + ks * 16;
                ldm_x4(afh[mt], sAh + e);
                ldm_x4(afl[mt], sAl + e);
            }
#pragma unroll
            for (int ntp = 0; ntp < 4; ntp++) {
                uint32_t bh[4], bl[4];
                int e = b_e0 + ntp * 16 * ASTRIDE + ks * 16;
                ldm_x4(bh, sBh + e);
                ldm_x4(bl, sBl + e);
#pragma unroll
                for (int mt = 0; mt < 2; mt++) {
                    mma_bf16(acc[mt][2 * ntp],     afh[mt], bh[0], bh[1]);
                    mma_bf16(acc[mt][2 * ntp],     afh[mt], bl[0], bl[1]);
                    mma_bf16(acc[mt][2 * ntp],     afl[mt], bh[0], bh[1]);
                    mma_bf16(acc[mt][2 * ntp + 1], afh[mt], bh[2], bh[3]);
                    mma_bf16(acc[mt][2 * ntp + 1], afh[mt], bl[2], bl[3]);
                    mma_bf16(acc[mt][2 * ntp + 1], afl[mt], bh[2], bh[3]);
                }
            }
        }
        __syncthreads();
    }
#undef ISSUE_STAGE

    // epilogue: c0,c1 at (row, 2*tig), c2,c3 at (row+8, 2*tig)
#pragma unroll
    for (int mt = 0; mt < 2; mt++) {
        int r0 = bm + warp_m + mt * 16 + grp;
#pragma unroll
        for (int nt = 0; nt < 8; nt++) {
            int col = bn + warp_n + nt * 8 + 2 * tig;
            float b0 = 0.f, b1 = 0.f;
            if (bias != nullptr) { b0 = bias[col]; b1 = bias[col + 1]; }
            float2 v0 = make_float2(acc[mt][nt][0] + b0, acc[mt][nt][1] + b1);
            float2 v1 = make_float2(acc[mt][nt][2] + b0, acc[mt][nt][3] + b1);
            *(float2*)(C + (size_t)r0 * N + col) = v0;
            *(float2*)(C + (size_t)(r0 + 8) * N + col) = v1;
        }
    }
}

// ---------------------------------------------------------------------------
// K2: sequential scan. Grid (G_GRP, B_DIM), 32 threads per CTA.
// Lane l owns 4 consecutive columns [4l, 4l+4). Depth-PFD register ring.
// ---------------------------------------------------------------------------
__device__ __forceinline__ float warp_allsum(float x) {
#pragma unroll
    for (int o = 16; o >= 1; o >>= 1)
        x += __shfl_xor_sync(0xffffffffu, x, o);
    return x;
}

__global__ void __launch_bounds__(32)
scan_kernel(const float* __restrict__ P, const float* __restrict__ state_in,
            float* __restrict__ opart, float* __restrict__ state_out)
{
    const int g = blockIdx.x;
    const int b = blockIdx.y;
    const int l = threadIdx.x;
    const int rowbase = g * R_ROWS;

    float4 st[R_ROWS];
    {
        const float* sb = state_in + ((size_t)b * F_DIM + rowbase) * F_DIM + 4 * l;
#pragma unroll
        for (int r = 0; r < R_ROWS; r++)
            st[r] = *(const float4*)(sb + r * F_DIM);
    }

    float4 pa[PFD], pb[PFD], pd[PFD], pg[PFD];
    float pc[PFD][R_ROWS], ps[PFD][R_ROWS];

#define LOADSTAGE(slot, tt) do {                                              \
    const float* _p = P + (size_t)((size_t)(tt) * B_DIM + b) * N6;            \
    float4 _a = *(const float4*)(_p + 0 * F_DIM + 4 * l);                     \
    float4 _b = *(const float4*)(_p + 1 * F_DIM + 4 * l);                     \
    float4 _d = *(const float4*)(_p + 3 * F_DIM + 4 * l);                     \
    float4 _i = *(const float4*)(_p + 4 * F_DIM + 4 * l);                     \
    pa[slot] = _a;                                                            \
    pb[slot] = make_float4(_b.x * INV_SQRT_F, _b.y * INV_SQRT_F,              \
                           _b.z * INV_SQRT_F, _b.w * INV_SQRT_F);             \
    pd[slot] = _d;                                                            \
    pg[slot] = make_float4(1.0f / (1.0f + __expf(-_i.x)),                     \
                           1.0f / (1.0f + __expf(-_i.y)),                     \
                           1.0f / (1.0f + __expf(-_i.z)),                     \
                           1.0f / (1.0f + __expf(-_i.w)));                    \
    _Pragma("unroll")                                                         \
    for (int _r = 0; _r < R_ROWS; _r++) {                                     \
        pc[slot][_r] = __ldg(_p + 2 * F_DIM + rowbase + _r);                  \
        ps[slot][_r] = __ldg(_p + 5 * F_DIM + rowbase + _r);                  \
    }                                                                         \
} while (0)

#pragma unroll
    for (int s = 0; s < PFD; s++) LOADSTAGE(s, s);

#pragma unroll 1
    for (int t0 = 0; t0 < T_DIM; t0 += PFD) {
#pragma unroll
        for (int ph = 0; ph < PFD; ph++) {
            const int t = t0 + ph;

            const float4 a = pa[ph];
            const float4 bb = pb[ph];
            const float4 dd = pd[ph];
            const float4 gg = pg[ph];

            float v[R_ROWS];
#pragma unroll
            for (int r = 0; r < R_ROWS; r++) {
                float m01 = fmaf(st[r].y, a.y, st[r].x * a.x);
                float m23 = fmaf(st[r].w, a.w, st[r].z * a.z);
                v[r] = m01 + m23;
            }
#pragma unroll
            for (int r = 0; r < R_ROWS; r++) v[r] = warp_allsum(v[r]);

#pragma unroll
            for (int r = 0; r < R_ROWS; r++) {
                const float cr = pc[ph][r];
                st[r].x = fmaf(st[r].x, gg.x, fmaf(v[r], bb.x, cr * dd.x));
                st[r].y = fmaf(st[r].y, gg.y, fmaf(v[r], bb.y, cr * dd.y));
                st[r].z = fmaf(st[r].z, gg.z, fmaf(v[r], bb.z, cr * dd.z));
                st[r].w = fmaf(st[r].w, gg.w, fmaf(v[r], bb.w, cr * dd.w));
            }

            float4 po = make_float4(0.f, 0.f, 0.f, 0.f);
#pragma unroll
            for (int r = 0; r < R_ROWS; r++) {
                const float sr = ps[ph][r];
                po.x = fmaf(sr, st[r].x, po.x);
                po.y = fmaf(sr, st[r].y, po.y);
                po.z = fmaf(sr, st[r].z, po.z);
                po.w = fmaf(sr, st[r].w, po.w);
            }
            float* ob = opart +
                ((size_t)((size_t)t * B_DIM + b) * G_GRP + g) * F_DIM + 4 * l;
            *(float4*)ob = po;

            {
                int tload = t + PFD;
                if (tload > T_DIM - 1) tload = T_DIM - 1;
                LOADSTAGE(ph, tload);
            }
        }
    }

    float* so = state_out + ((size_t)b * F_DIM + rowbase) * F_DIM + 4 * l;
#pragma unroll
    for (int r = 0; r < R_ROWS; r++)
        *(float4*)(so + r * F_DIM) = st[r];
#undef LOADSTAGE
}

// ---------------------------------------------------------------------------
// K3: reduce partial outputs over G, emitting bf16 hi/lo for K4
// ---------------------------------------------------------------------------
__global__ void reduce_opart_kernel(const float* __restrict__ opart)
{
    const int F4 = F_DIM / 4;
    size_t idx = (size_t)blockIdx.x * blockDim.x + threadIdx.x;
    size_t total = (size_t)M_DIM * F4;
    if (idx >= total) return;
    size_t row = idx / F4;
    int f4 = (int)(idx % F4);
    const float4* src = (const float4*)opart + row * (size_t)(G_GRP * F4) + f4;
    float4 acc = make_float4(0.f, 0.f, 0.f, 0.f);
#pragma unroll
    for (int gg = 0; gg < G_GRP; gg++) {
        float4 xv = src[(size_t)gg * F4];
        acc.x += xv.x; acc.y += xv.y; acc.z += xv.z; acc.w += xv.w;
    }
    __nv_bfloat16 h0, l0, h1, l1, h2, l2, h3, l3;
    split1(acc.x, h0, l0); split1(acc.y, h1, l1);
    split1(acc.z, h2, l2); split1(acc.w, h3, l3);
    uint2 ph, pl;
    ph.x = (uint32_t)__bfloat16_as_ushort(h0) | ((uint32_t)__bfloat16_as_ushort(h1) << 16);
    ph.y = (uint32_t)__bfloat16_as_ushort(h2) | ((uint32_t)__bfloat16_as_ushort(h3) << 16);
    pl.x = (uint32_t)__bfloat16_as_ushort(l0) | ((uint32_t)__bfloat16_as_ushort(l1) << 16);
    pl.y = (uint32_t)__bfloat16_as_ushort(l2) | ((uint32_t)__bfloat16_as_ushort(l3) << 16);
    ((uint2*)d_oh)[idx] = ph;
    ((uint2*)d_ol)[idx] = pl;
}

// ---------------------------------------------------------------------------
// launch
// ---------------------------------------------------------------------------
extern "C" void kernel_launch(void* const* d_in, const int* in_sizes, int n_in,
                              void* d_out, int out_size)
{
    const float* x     = (const float*)d_in[0];
    const float* state = (const float*)d_in[1];
    const float* A_w = (const float*)d_in[2];
    const float* A_b = (const float*)d_in[3];
    const float* B_w = (const float*)d_in[4];
    const float* B_b = (const float*)d_in[5];
    const float* C_w = (const float*)d_in[6];
    const float* C_b = (const float*)d_in[7];
    const float* D_w = (const float*)d_in[8];
    const float* D_b = (const float*)d_in[9];
    const float* I_w = (const float*)d_in[10];
    const float* I_b = (const float*)d_in[11];
    const float* S_w = (const float*)d_in[12];
    const float* S_b = (const float*)d_in[13];
    const float* O_w = (const float*)d_in[14];

    float* out = (float*)d_out;

    float *b6, *P, *opart, *stfb;
    __nv_bfloat16 *xh, *xl, *W6h, *W6l, *Owh, *Owl, *oh, *ol;
    cudaGetSymbolAddress((void**)&b6, d_b6);
    cudaGetSymbolAddress((void**)&P, d_P);
    cudaGetSymbolAddress((void**)&opart, d_opart);
    cudaGetSymbolAddress((void**)&stfb, d_stfb);
    cudaGetSymbolAddress((void**)&xh, d_xh);
    cudaGetSymbolAddress((void**)&xl, d_xl);
    cudaGetSymbolAddress((void**)&W6h, d_W6h);
    cudaGetSymbolAddress((void**)&W6l, d_W6l);
    cudaGetSymbolAddress((void**)&Owh, d_Owh);
    cudaGetSymbolAddress((void**)&Owl, d_Owl);
    cudaGetSymbolAddress((void**)&oh, d_oh);
    cudaGetSymbolAddress((void**)&ol, d_ol);

    cudaFuncSetAttribute(bf16_gemm_async,
                         cudaFuncAttributeMaxDynamicSharedMemorySize, GEMM_SMEM);

    const size_t y_elems = (size_t)M_DIM * C_DIM;
    const size_t st_elems = (size_t)B_DIM * F_DIM * F_DIM;
    float* y = out;
    float* state_out =
        ((size_t)out_size >= y_elems + st_elems) ? (out + y_elems) : stfb;

    // pos 1: pack + split weights
    pack_weights_kernel<<<(F_DIM * C_DIM + 255) / 256, 256>>>(
        A_w, B_w, C_w, D_w, I_w, S_w, A_b, B_b, C_b, D_b, I_b, S_b, O_w);

    // pos 2: split x
    {
        size_t total4 = (size_t)M_DIM * C_DIM / 4;
        split_x_kernel<<<(unsigned)((total4 + 255) / 256), 256>>>(x);
    }

    // pos 3: noop (keeps K1 at ncu capture position 4)
    noop_kernel<<<1, 1>>>();

    // pos 4: K1  P = x @ W6^T + b6  (M=32768, N=768, K=1024)
    {
        dim3 grid(N6 / 128, M_DIM / 128);
        bf16_gemm_async<<<grid, 256, GEMM_SMEM>>>(xh, xl, W6h, W6l, b6, P,
                                                  M_DIM, N6, C_DIM);
    }

    // pos 5: scan
    {
        dim3 grid(G_GRP, B_DIM);
        scan_kernel<<<grid, 32>>>(P, state, opart, state_out);
    }

    // pos 6: reduce partials -> bf16 hi/lo o
    {
        size_t total = (size_t)M_DIM * (F_DIM / 4);
        reduce_opart_kernel<<<(unsigned)((total + 255) / 256), 256>>>(opart);
    }

    // pos 7: K4  y = o @ O_w^T  (M=32768, N=1024, K=128)
    {
        dim3 grid(C_DIM / 128, M_DIM / 128);
        bf16_gemm_async<<<grid, 256, GEMM_SMEM>>>(oh, ol, Owh, Owl, nullptr, y,
                                                  M_DIM, C_DIM, F_DIM);
    }
}

// round 9
// speedup vs baseline: 2.2630x; 1.0523x over previous
#include <cuda_runtime.h>
#include <cuda_bf16.h>
#include <math.h>
#include <stdint.h>

// Problem dims
#define T_DIM 4096
#define B_DIM 8
#define C_DIM 1024
#define F_DIM 128
#define NPROJ 6
#define N6 (NPROJ * F_DIM)          // 768
#define M_DIM (T_DIM * B_DIM)       // 32768
#define G_GRP 32                    // row groups per batch for scan
#define R_ROWS (F_DIM / G_GRP)      // 4 rows per warp

#define INV_SQRT_F 0.08838834764831845f  // 1/sqrt(128)

// Scan SMEM pipeline
#define CHUNK 16                    // steps per chunk
#define SLOT_F 528                  // floats per step slot (4*128 + 4 + 4 + pad)
#define BUF_F (CHUNK * SLOT_F)      // floats per chunk buffer
#define SCAN_SMEM (2 * BUF_F * 4)   // bytes (67584)

// ---------------------------------------------------------------------------
// Scratch (static device arrays: allocation-free per harness rules)
// ---------------------------------------------------------------------------
__device__ float d_b6[N6];                                            // packed biases
__device__ float d_P[(size_t)M_DIM * N6];                             // 96 MB projections
__device__ float d_opart[(size_t)M_DIM * G_GRP * F_DIM];              // 512 MB partials
__device__ float d_stfb[(size_t)B_DIM * F_DIM * F_DIM];               // state fallback
__device__ __nv_bfloat16 d_xh[(size_t)M_DIM * C_DIM];                 // 64 MB x hi
__device__ __nv_bfloat16 d_xl[(size_t)M_DIM * C_DIM];                 // 64 MB x lo
__device__ __nv_bfloat16 d_W6h[(size_t)N6 * C_DIM];                   // 1.5 MB
__device__ __nv_bfloat16 d_W6l[(size_t)N6 * C_DIM];                   // 1.5 MB
__device__ __nv_bfloat16 d_Owh[(size_t)C_DIM * F_DIM];
__device__ __nv_bfloat16 d_Owl[(size_t)C_DIM * F_DIM];
__device__ __nv_bfloat16 d_oh[(size_t)M_DIM * F_DIM];                 // 8 MB
__device__ __nv_bfloat16 d_ol[(size_t)M_DIM * F_DIM];                 // 8 MB

// ---------------------------------------------------------------------------
// helpers
// ---------------------------------------------------------------------------
__device__ __forceinline__ void split1(float v, __nv_bfloat16& h, __nv_bfloat16& l) {
    h = __float2bfloat16_rn(v);
    l = __float2bfloat16_rn(v - __bfloat162float(h));
}

__device__ __forceinline__ void cp16(uint32_t dst, const void* src) {
    asm volatile("cp.async.ca.shared.global [%0], [%1], 16;"
                 :: "r"(dst), "l"(src));
}

// ---------------------------------------------------------------------------
// K0: pack biases + split all weights into bf16 hi/lo
// ---------------------------------------------------------------------------
__global__ void pack_weights_kernel(
    const float* __restrict__ Aw, const float* __restrict__ Bw,
    const float* __restrict__ Cw, const float* __restrict__ Dw,
    const float* __restrict__ Iw, const float* __restrict__ Sw,
    const float* __restrict__ Ab, const float* __restrict__ Bb,
    const float* __restrict__ Cb, const float* __restrict__ Db,
    const float* __restrict__ Ib, const float* __restrict__ Sb,
    const float* __restrict__ Ow)
{
    const int per = F_DIM * C_DIM;  // 131072
    int i = blockIdx.x * blockDim.x + threadIdx.x;
    if (i < per) {
        split1(Aw[i], d_W6h[0 * per + i], d_W6l[0 * per + i]);
        split1(Bw[i], d_W6h[1 * per + i], d_W6l[1 * per + i]);
        split1(Cw[i], d_W6h[2 * per + i], d_W6l[2 * per + i]);
        split1(Dw[i], d_W6h[3 * per + i], d_W6l[3 * per + i]);
        split1(Iw[i], d_W6h[4 * per + i], d_W6l[4 * per + i]);
        split1(Sw[i], d_W6h[5 * per + i], d_W6l[5 * per + i]);
        split1(Ow[i], d_Owh[i], d_Owl[i]);
    }
    if (i < F_DIM) {
        d_b6[0 * F_DIM + i] = Ab[i];
        d_b6[1 * F_DIM + i] = Bb[i];
        d_b6[2 * F_DIM + i] = Cb[i];
        d_b6[3 * F_DIM + i] = Db[i];
        d_b6[4 * F_DIM + i] = Ib[i];
        d_b6[5 * F_DIM + i] = Sb[i];
    }
}

// ---------------------------------------------------------------------------
// K0b: split x into bf16 hi/lo
// ---------------------------------------------------------------------------
__global__ void split_x_kernel(const float* __restrict__ in)
{
    size_t i4 = (size_t)blockIdx.x * blockDim.x + threadIdx.x;
    size_t total4 = (size_t)M_DIM * C_DIM / 4;
    if (i4 >= total4) return;
    float4 v = ((const float4*)in)[i4];
    __nv_bfloat16 h0, l0, h1, l1, h2, l2, h3, l3;
    split1(v.x, h0, l0); split1(v.y, h1, l1);
    split1(v.z, h2, l2); split1(v.w, h3, l3);
    uint2 ph, pl;
    ph.x = (uint32_t)__bfloat16_as_ushort(h0) | ((uint32_t)__bfloat16_as_ushort(h1) << 16);
    ph.y = (uint32_t)__bfloat16_as_ushort(h2) | ((uint32_t)__bfloat16_as_ushort(h3) << 16);
    pl.x = (uint32_t)__bfloat16_as_ushort(l0) | ((uint32_t)__bfloat16_as_ushort(l1) << 16);
    pl.y = (uint32_t)__bfloat16_as_ushort(l2) | ((uint32_t)__bfloat16_as_ushort(l3) << 16);
    ((uint2*)d_xh)[i4] = ph;
    ((uint2*)d_xl)[i4] = pl;
}

// ---------------------------------------------------------------------------
// K1/K4: 3xBF16 GEMM, cp.async 2-stage pipeline + ldmatrix + mma.m16n8k16 (NT)
// ---------------------------------------------------------------------------
#define ASTRIDE 40
#define TILE_E (128 * ASTRIDE)
#define TILE_B (TILE_E * 2)
#define STAGE_B (4 * TILE_B)
#define GEMM_SMEM (2 * STAGE_B)

__device__ __forceinline__ void ldm_x4(uint32_t (&r)[4], const __nv_bfloat16* p) {
    uint32_t addr = (uint32_t)__cvta_generic_to_shared(p);
    asm volatile("ldmatrix.sync.aligned.m8n8.x4.shared.b16 {%0,%1,%2,%3}, [%4];"
                 : "=r"(r[0]), "=r"(r[1]), "=r"(r[2]), "=r"(r[3]) : "r"(addr));
}

__device__ __forceinline__ void mma_bf16(float* d, const uint32_t* a,
                                         uint32_t b0, uint32_t b1) {
    asm volatile(
        "mma.sync.aligned.m16n8k16.row.col.f32.bf16.bf16.f32 "
        "{%0,%1,%2,%3}, {%4,%5,%6,%7}, {%8,%9}, {%0,%1,%2,%3};"
        : "+f"(d[0]), "+f"(d[1]), "+f"(d[2]), "+f"(d[3])
        : "r"(a[0]), "r"(a[1]), "r"(a[2]), "r"(a[3]), "r"(b0), "r"(b1));
}

__global__ void __launch_bounds__(256, 2)
bf16_gemm_async(const __nv_bfloat16* __restrict__ Ah,
                const __nv_bfloat16* __restrict__ Al,
                const __nv_bfloat16* __restrict__ Bh,
                const __nv_bfloat16* __restrict__ Bl,
                const float* __restrict__ bias, float* __restrict__ C,
                int M, int N, int K)
{
    extern __shared__ __align__(16) __nv_bfloat16 smd[];

    const int tid = threadIdx.x;
    const int wid = tid >> 5;
    const int lane = tid & 31;
    const int grp = lane >> 2;
    const int tig = lane & 3;

    const int bm = blockIdx.y * 128;
    const int bn = blockIdx.x * 128;
    const int warp_m = (wid >> 1) * 32;
    const int warp_n = (wid & 1) * 64;

    float acc[2][8][4];
#pragma unroll
    for (int mt = 0; mt < 2; mt++)
#pragma unroll
        for (int nt = 0; nt < 8; nt++)
#pragma unroll
            for (int q = 0; q < 4; q++) acc[mt][nt][q] = 0.0f;

    const int lrow = tid >> 1;
    const int cb = (tid & 1) * 2;

    const __nv_bfloat16* gsrc[4];
    gsrc[0] = Ah + (size_t)(bm + lrow) * K;
    gsrc[1] = Al + (size_t)(bm + lrow) * K;
    gsrc[2] = Bh + (size_t)(bn + lrow) * K;
    gsrc[3] = Bl + (size_t)(bn + lrow) * K;

    const uint32_t smem_base = (uint32_t)__cvta_generic_to_shared(smd);
    const uint32_t dst0 = smem_base + (uint32_t)(lrow * ASTRIDE * 2 + cb * 16);

    const int a_e0 = (warp_m + (lane & 15)) * ASTRIDE + ((lane >> 4) & 1) * 8;
    const int b_e0 = (warp_n + (lane & 7) + ((lane >> 4) & 1) * 8) * ASTRIDE
                   + ((lane >> 3) & 1) * 8;

#define ISSUE_STAGE(stg, kk) do {                                          \
    uint32_t _d = dst0 + (uint32_t)(stg) * STAGE_B;                        \
    _Pragma("unroll")                                                      \
    for (int _m = 0; _m < 4; _m++) {                                       \
        cp16(_d + 0,  gsrc[_m] + (kk) + (cb + 0) * 8);                     \
        cp16(_d + 16, gsrc[_m] + (kk) + (cb + 1) * 8);                     \
        _d += TILE_B;                                                      \
    }                                                                      \
    asm volatile("cp.async.commit_group;");                                \
} while (0)

    const int niter = K >> 5;
    ISSUE_STAGE(0, 0);

    for (int i = 0; i < niter; i++) {
        if (i + 1 < niter) {
            ISSUE_STAGE((i + 1) & 1, (i + 1) * 32);
            asm volatile("cp.async.wait_group 1;");
        } else {
            asm volatile("cp.async.wait_group 0;");
        }
        __syncthreads();

        const __nv_bfloat16* sAh = smd + (size_t)((i & 1) * 4 + 0) * TILE_E;
        const __nv_bfloat16* sAl = smd + (size_t)((i & 1) * 4 + 1) * TILE_E;
        const __nv_bfloat16* sBh = smd + (size_t)((i & 1) * 4 + 2) * TILE_E;
        const __nv_bfloat16* sBl = smd + (size_t)((i & 1) * 4 + 3) * TILE_E;

#pragma unroll
        for (int ks = 0; ks < 2; ks++) {
            uint32_t afh[2][4], afl[2][4];
#pragma unroll
            for (int mt = 0; mt < 2; mt++) {
                int e = a_e0 + mt * 16 * ASTRIDE + ks * 16;
                ldm_x4(afh[mt], sAh + e);
                ldm_x4(afl[mt], sAl + e);
            }
#pragma unroll
            for (int ntp = 0; ntp < 4; ntp++) {
                uint32_t bh[4], bl[4];
                int e = b_e0 + ntp * 16 * ASTRIDE + ks * 16;
                ldm_x4(bh, sBh + e);
                ldm_x4(bl, sBl + e);
#pragma unroll
                for (int mt = 0; mt < 2; mt++) {
                    mma_bf16(acc[mt][2 * ntp],     afh[mt], bh[0], bh[1]);
                    mma_bf16(acc[mt][2 * ntp],     afh[mt], bl[0], bl[1]);
                    mma_bf16(acc[mt][2 * ntp],     afl[mt], bh[0], bh[1]);
                    mma_bf16(acc[mt][2 * ntp + 1], afh[mt], bh[2], bh[3]);
                    mma_bf16(acc[mt][2 * ntp + 1], afh[mt], bl[2], bl[3]);
                    mma_bf16(acc[mt][2 * ntp + 1], afl[mt], bh[2], bh[3]);
                }
            }
        }
        __syncthreads();
    }
#undef ISSUE_STAGE

#pragma unroll
    for (int mt = 0; mt < 2; mt++) {
        int r0 = bm + warp_m + mt * 16 + grp;
#pragma unroll
        for (int nt = 0; nt < 8; nt++) {
            int col = bn + warp_n + nt * 8 + 2 * tig;
            float b0 = 0.f, b1 = 0.f;
            if (bias != nullptr) { b0 = bias[col]; b1 = bias[col + 1]; }
            float2 v0 = make_float2(acc[mt][nt][0] + b0, acc[mt][nt][1] + b1);
            float2 v1 = make_float2(acc[mt][nt][2] + b0, acc[mt][nt][3] + b1);
            *(float2*)(C + (size_t)r0 * N + col) = v0;
            *(float2*)(C + (size_t)(r0 + 8) * N + col) = v1;
        }
    }
}

// ---------------------------------------------------------------------------
// K2: sequential scan with SMEM chunk pipeline.
// Grid (G_GRP, B_DIM), 32 threads per CTA. Lane l owns columns [4l, 4l+4).
// P consumed via 2-buffer ring of 16-step chunks loaded with cp.async
// (one commit group per chunk); per-step reads are conflict-free LDS.
// Slot layout (floats): a[0..127], b[128..255], d[256..383], i[384..511],
//                       c[512..515], s[516..519], pad[520..527]
// ---------------------------------------------------------------------------
__device__ __forceinline__ float warp_allsum(float x) {
#pragma unroll
    for (int o = 16; o >= 1; o >>= 1)
        x += __shfl_xor_sync(0xffffffffu, x, o);
    return x;
}

__global__ void __launch_bounds__(32)
scan_kernel(const float* __restrict__ P, const float* __restrict__ state_in,
            float* __restrict__ opart, float* __restrict__ state_out)
{
    extern __shared__ __align__(16) float sm[];

    const int g = blockIdx.x;
    const int b = blockIdx.y;
    const int l = threadIdx.x;
    const int rowbase = g * R_ROWS;

    const uint32_t smb = (uint32_t)__cvta_generic_to_shared(sm);

    // chunk issue: lane copies 4 16B chunks (a,b,d,i) per slot; lanes 0,1 add c,s
#define ISSUE_CHUNK(cc, bi) do {                                              \
    const int _t0 = (cc) * CHUNK;                                             \
    _Pragma("unroll 4")                                                       \
    for (int _s = 0; _s < CHUNK; _s++) {                                      \
        const float* _src = P + (size_t)((size_t)(_t0 + _s) * B_DIM + b) * N6;\
        uint32_t _dst = smb + (uint32_t)(((bi) * BUF_F + _s * SLOT_F) * 4);   \
        cp16(_dst + (uint32_t)(l * 16),          _src + 0 * F_DIM + l * 4);   \
        cp16(_dst + (uint32_t)(512 + l * 16),    _src + 1 * F_DIM + l * 4);   \
        cp16(_dst + (uint32_t)(1024 + l * 16),   _src + 3 * F_DIM + l * 4);   \
        cp16(_dst + (uint32_t)(1536 + l * 16),   _src + 4 * F_DIM + l * 4);   \
        if (l == 0) cp16(_dst + 2048, _src + 2 * F_DIM + rowbase);            \
        if (l == 1) cp16(_dst + 2064, _src + 5 * F_DIM + rowbase);            \
    }                                                                         \
    asm volatile("cp.async.commit_group;");                                   \
} while (0)

    // initial state
    float4 st[R_ROWS];
    {
        const float* sb = state_in + ((size_t)b * F_DIM + rowbase) * F_DIM + 4 * l;
#pragma unroll
        for (int r = 0; r < R_ROWS; r++)
            st[r] = *(const float4*)(sb + r * F_DIM);
    }

    ISSUE_CHUNK(0, 0);
    ISSUE_CHUNK(1, 1);

    const int NCHUNK = T_DIM / CHUNK;   // 256
#pragma unroll 1
    for (int cc = 0; cc < NCHUNK; cc++) {
        asm volatile("cp.async.wait_group 1;");
        __syncwarp();

        const int bi = cc & 1;
        const float* buf = sm + (size_t)bi * BUF_F;

#pragma unroll 4
        for (int s = 0; s < CHUNK; s++) {
            const int t = cc * CHUNK + s;
            const float* sp = buf + s * SLOT_F;

            float4 a  = *(const float4*)(sp + 4 * l);
            float4 bv = *(const float4*)(sp + 128 + 4 * l);
            float4 dd = *(const float4*)(sp + 256 + 4 * l);
            float4 iv = *(const float4*)(sp + 384 + 4 * l);

            // v[r] = row r of old state dot a
            float v[R_ROWS];
#pragma unroll
            for (int r = 0; r < R_ROWS; r++) {
                float m01 = fmaf(st[r].y, a.y, st[r].x * a.x);
                float m23 = fmaf(st[r].w, a.w, st[r].z * a.z);
                v[r] = m01 + m23;
            }
#pragma unroll
            for (int r = 0; r < R_ROWS; r++) v[r] = warp_allsum(v[r]);

            // transforms (overlap the shfl window)
            float4 gg = make_float4(1.0f / (1.0f + __expf(-iv.x)),
                                    1.0f / (1.0f + __expf(-iv.y)),
                                    1.0f / (1.0f + __expf(-iv.z)),
                                    1.0f / (1.0f + __expf(-iv.w)));
            float4 bb = make_float4(bv.x * INV_SQRT_F, bv.y * INV_SQRT_F,
                                    bv.z * INV_SQRT_F, bv.w * INV_SQRT_F);
            float cc4[R_ROWS], ss4[R_ROWS];
#pragma unroll
            for (int r = 0; r < R_ROWS; r++) {
                cc4[r] = sp[512 + r];
                ss4[r] = sp[516 + r];
            }

            // st = st*g + v*b + c*d
#pragma unroll
            for (int r = 0; r < R_ROWS; r++) {
                const float cr = cc4[r];
                st[r].x = fmaf(st[r].x, gg.x, fmaf(v[r], bb.x, cr * dd.x));
                st[r].y = fmaf(st[r].y, gg.y, fmaf(v[r], bb.y, cr * dd.y));
                st[r].z = fmaf(st[r].z, gg.z, fmaf(v[r], bb.z, cr * dd.z));
                st[r].w = fmaf(st[r].w, gg.w, fmaf(v[r], bb.w, cr * dd.w));
            }

            // partial output over owned rows
            float4 po = make_float4(0.f, 0.f, 0.f, 0.f);
#pragma unroll
            for (int r = 0; r < R_ROWS; r++) {
                const float sr = ss4[r];
                po.x = fmaf(sr, st[r].x, po.x);
                po.y = fmaf(sr, st[r].y, po.y);
                po.z = fmaf(sr, st[r].z, po.z);
                po.w = fmaf(sr, st[r].w, po.w);
            }
            float* ob = opart +
                ((size_t)((size_t)t * B_DIM + b) * G_GRP + g) * F_DIM + 4 * l;
            *(float4*)ob = po;
        }

        // buffer bi fully consumed; refill with chunk cc+2
        __syncwarp();
        if (cc + 2 < NCHUNK) ISSUE_CHUNK(cc + 2, bi);
    }
#undef ISSUE_CHUNK

    float* so = state_out + ((size_t)b * F_DIM + rowbase) * F_DIM + 4 * l;
#pragma unroll
    for (int r = 0; r < R_ROWS; r++)
        *(float4*)(so + r * F_DIM) = st[r];
}

// ---------------------------------------------------------------------------
// K3: reduce partial outputs over G, emitting bf16 hi/lo for K4
// ---------------------------------------------------------------------------
__global__ void reduce_opart_kernel(const float* __restrict__ opart)
{
    const int F4 = F_DIM / 4;
    size_t idx = (size_t)blockIdx.x * blockDim.x + threadIdx.x;
    size_t total = (size_t)M_DIM * F4;
    if (idx >= total) return;
    size_t row = idx / F4;
    int f4 = (int)(idx % F4);
    const float4* src = (const float4*)opart + row * (size_t)(G_GRP * F4) + f4;
    float4 acc = make_float4(0.f, 0.f, 0.f, 0.f);
#pragma unroll
    for (int gg = 0; gg < G_GRP; gg++) {
        float4 xv = src[(size_t)gg * F4];
        acc.x += xv.x; acc.y += xv.y; acc.z += xv.z; acc.w += xv.w;
    }
    __nv_bfloat16 h0, l0, h1, l1, h2, l2, h3, l3;
    split1(acc.x, h0, l0); split1(acc.y, h1, l1);
    split1(acc.z, h2, l2); split1(acc.w, h3, l3);
    uint2 ph, pl;
    ph.x = (uint32_t)__bfloat16_as_ushort(h0) | ((uint32_t)__bfloat16_as_ushort(h1) << 16);
    ph.y = (uint32_t)__bfloat16_as_ushort(h2) | ((uint32_t)__bfloat16_as_ushort(h3) << 16);
    pl.x = (uint32_t)__bfloat16_as_ushort(l0) | ((uint32_t)__bfloat16_as_ushort(l1) << 16);
    pl.y = (uint32_t)__bfloat16_as_ushort(l2) | ((uint32_t)__bfloat16_as_ushort(l3) << 16);
    ((uint2*)d_oh)[idx] = ph;
    ((uint2*)d_ol)[idx] = pl;
}

// ---------------------------------------------------------------------------
// launch
// ---------------------------------------------------------------------------
extern "C" void kernel_launch(void* const* d_in, const int* in_sizes, int n_in,
                              void* d_out, int out_size)
{
    const float* x     = (const float*)d_in[0];
    const float* state = (const float*)d_in[1];
    const float* A_w = (const float*)d_in[2];
    const float* A_b = (const float*)d_in[3];
    const float* B_w = (const float*)d_in[4];
    const float* B_b = (const float*)d_in[5];
    const float* C_w = (const float*)d_in[6];
    const float* C_b = (const float*)d_in[7];
    const float* D_w = (const float*)d_in[8];
    const float* D_b = (const float*)d_in[9];
    const float* I_w = (const float*)d_in[10];
    const float* I_b = (const float*)d_in[11];
    const float* S_w = (const float*)d_in[12];
    const float* S_b = (const float*)d_in[13];
    const float* O_w = (const float*)d_in[14];

    float* out = (float*)d_out;

    float *b6, *P, *opart, *stfb;
    __nv_bfloat16 *xh, *xl, *W6h, *W6l, *Owh, *Owl, *oh, *ol;
    cudaGetSymbolAddress((void**)&b6, d_b6);
    cudaGetSymbolAddress((void**)&P, d_P);
    cudaGetSymbolAddress((void**)&opart, d_opart);
    cudaGetSymbolAddress((void**)&stfb, d_stfb);
    cudaGetSymbolAddress((void**)&xh, d_xh);
    cudaGetSymbolAddress((void**)&xl, d_xl);
    cudaGetSymbolAddress((void**)&W6h, d_W6h);
    cudaGetSymbolAddress((void**)&W6l, d_W6l);
    cudaGetSymbolAddress((void**)&Owh, d_Owh);
    cudaGetSymbolAddress((void**)&Owl, d_Owl);
    cudaGetSymbolAddress((void**)&oh, d_oh);
    cudaGetSymbolAddress((void**)&ol, d_ol);

    cudaFuncSetAttribute(bf16_gemm_async,
                         cudaFuncAttributeMaxDynamicSharedMemorySize, GEMM_SMEM);
    cudaFuncSetAttribute(scan_kernel,
                         cudaFuncAttributeMaxDynamicSharedMemorySize, SCAN_SMEM);

    const size_t y_elems = (size_t)M_DIM * C_DIM;
    const size_t st_elems = (size_t)B_DIM * F_DIM * F_DIM;
    float* y = out;
    float* state_out =
        ((size_t)out_size >= y_elems + st_elems) ? (out + y_elems) : stfb;

    // pos 1: pack + split weights
    pack_weights_kernel<<<(F_DIM * C_DIM + 255) / 256, 256>>>(
        A_w, B_w, C_w, D_w, I_w, S_w, A_b, B_b, C_b, D_b, I_b, S_b, O_w);

    // pos 2: split x
    {
        size_t total4 = (size_t)M_DIM * C_DIM / 4;
        split_x_kernel<<<(unsigned)((total4 + 255) / 256), 256>>>(x);
    }

    // pos 3: K1  P = x @ W6^T + b6  (M=32768, N=768, K=1024)
    {
        dim3 grid(N6 / 128, M_DIM / 128);
        bf16_gemm_async<<<grid, 256, GEMM_SMEM>>>(xh, xl, W6h, W6l, b6, P,
                                                  M_DIM, N6, C_DIM);
    }

    // pos 4: scan (ncu capture position)
    {
        dim3 grid(G_GRP, B_DIM);
        scan_kernel<<<grid, 32, SCAN_SMEM>>>(P, state, opart, state_out);
    }

    // pos 5: reduce partials -> bf16 hi/lo o
    {
        size_t total = (size_t)M_DIM * (F_DIM / 4);
        reduce_opart_kernel<<<(unsigned)((total + 255) / 256), 256>>>(opart);
    }

    // pos 6: K4  y = o @ O_w^T  (M=32768, N=1024, K=128)
    {
        dim3 grid(C_DIM / 128, M_DIM / 128);
        bf16_gemm_async<<<grid, 256, GEMM_SMEM>>>(oh, ol, Owh, Owl, nullptr, y,
                                                  M_DIM, C_DIM, F_DIM);
    }
}

// round 10
// speedup vs baseline: 3.4584x; 1.5282x over previous
#include <cuda_runtime.h>
#include <cuda_bf16.h>
#include <math.h>
#include <stdint.h>

// Problem dims
#define T_DIM 4096
#define B_DIM 8
#define C_DIM 1024
#define F_DIM 128
#define NPROJ 6
#define N6 (NPROJ * F_DIM)          // 768
#define M_DIM (T_DIM * B_DIM)       // 32768
#define G_GRP 32                    // row groups per batch for scan
#define R_ROWS (F_DIM / G_GRP)      // 4 rows per warp

#define INV_SQRT_F 0.08838834764831845f  // 1/sqrt(128)

// Scan SMEM pipeline
#define CHUNK 16                    // steps per chunk
#define SLOT_F 528                  // floats per step slot (4*128 + 4 + 4 + pad)
#define BUF_F (CHUNK * SLOT_F)      // floats per chunk buffer
#define SCAN_SMEM (2 * BUF_F * 4)   // bytes (67584)

// ---------------------------------------------------------------------------
// Scratch (static device arrays: allocation-free per harness rules)
// ---------------------------------------------------------------------------
__device__ float d_b6[N6];                                            // packed biases
__device__ float d_P[(size_t)M_DIM * N6];                             // 96 MB projections
__device__ float d_opart[(size_t)M_DIM * G_GRP * F_DIM];              // 512 MB partials
__device__ float d_stfb[(size_t)B_DIM * F_DIM * F_DIM];               // state fallback
__device__ __nv_bfloat16 d_xh[(size_t)M_DIM * C_DIM];                 // 64 MB x hi
__device__ __nv_bfloat16 d_xl[(size_t)M_DIM * C_DIM];                 // 64 MB x lo
__device__ __nv_bfloat16 d_W6h[(size_t)N6 * C_DIM];                   // 1.5 MB
__device__ __nv_bfloat16 d_W6l[(size_t)N6 * C_DIM];                   // 1.5 MB
__device__ __nv_bfloat16 d_Owh[(size_t)C_DIM * F_DIM];
__device__ __nv_bfloat16 d_Owl[(size_t)C_DIM * F_DIM];
__device__ __nv_bfloat16 d_oh[(size_t)M_DIM * F_DIM];                 // 8 MB
__device__ __nv_bfloat16 d_ol[(size_t)M_DIM * F_DIM];                 // 8 MB

// ---------------------------------------------------------------------------
// helpers
// ---------------------------------------------------------------------------
__device__ __forceinline__ void split1(float v, __nv_bfloat16& h, __nv_bfloat16& l) {
    h = __float2bfloat16_rn(v);
    l = __float2bfloat16_rn(v - __bfloat162float(h));
}

__device__ __forceinline__ void cp16(uint32_t dst, const void* src) {
    asm volatile("cp.async.ca.shared.global [%0], [%1], 16;"
                 :: "r"(dst), "l"(src));
}

// dummy kernel: keeps the scan at ncu capture position 4
__global__ void noop_kernel() {}

// ---------------------------------------------------------------------------
// K0: pack biases + split weights AND x into bf16 hi/lo (merged kernel)
// ---------------------------------------------------------------------------
__global__ void pack_split_kernel(
    const float* __restrict__ xin,
    const float* __restrict__ Aw, const float* __restrict__ Bw,
    const float* __restrict__ Cw, const float* __restrict__ Dw,
    const float* __restrict__ Iw, const float* __restrict__ Sw,
    const float* __restrict__ Ab, const float* __restrict__ Bb,
    const float* __restrict__ Cb, const float* __restrict__ Db,
    const float* __restrict__ Ib, const float* __restrict__ Sb,
    const float* __restrict__ Ow)
{
    size_t i4 = (size_t)blockIdx.x * blockDim.x + threadIdx.x;
    const size_t total4 = (size_t)M_DIM * C_DIM / 4;
    if (i4 < total4) {
        float4 v = ((const float4*)xin)[i4];
        __nv_bfloat16 h0, l0, h1, l1, h2, l2, h3, l3;
        split1(v.x, h0, l0); split1(v.y, h1, l1);
        split1(v.z, h2, l2); split1(v.w, h3, l3);
        uint2 ph, pl;
        ph.x = (uint32_t)__bfloat16_as_ushort(h0) | ((uint32_t)__bfloat16_as_ushort(h1) << 16);
        ph.y = (uint32_t)__bfloat16_as_ushort(h2) | ((uint32_t)__bfloat16_as_ushort(h3) << 16);
        pl.x = (uint32_t)__bfloat16_as_ushort(l0) | ((uint32_t)__bfloat16_as_ushort(l1) << 16);
        pl.y = (uint32_t)__bfloat16_as_ushort(l2) | ((uint32_t)__bfloat16_as_ushort(l3) << 16);
        ((uint2*)d_xh)[i4] = ph;
        ((uint2*)d_xl)[i4] = pl;
    }
    const size_t per = (size_t)F_DIM * C_DIM;  // 131072
    if (i4 < per) {
        size_t i = i4;
        split1(Aw[i], d_W6h[0 * per + i], d_W6l[0 * per + i]);
        split1(Bw[i], d_W6h[1 * per + i], d_W6l[1 * per + i]);
        split1(Cw[i], d_W6h[2 * per + i], d_W6l[2 * per + i]);
        split1(Dw[i], d_W6h[3 * per + i], d_W6l[3 * per + i]);
        split1(Iw[i], d_W6h[4 * per + i], d_W6l[4 * per + i]);
        split1(Sw[i], d_W6h[5 * per + i], d_W6l[5 * per + i]);
        split1(Ow[i], d_Owh[i], d_Owl[i]);
    }
    if (i4 < F_DIM) {
        size_t i = i4;
        d_b6[0 * F_DIM + i] = Ab[i];
        d_b6[1 * F_DIM + i] = Bb[i];
        d_b6[2 * F_DIM + i] = Cb[i];
        d_b6[3 * F_DIM + i] = Db[i];
        d_b6[4 * F_DIM + i] = Ib[i];
        d_b6[5 * F_DIM + i] = Sb[i];
    }
}

// ---------------------------------------------------------------------------
// K1/K4: 3xBF16 GEMM, cp.async 2-stage pipeline + ldmatrix + mma.m16n8k16 (NT)
// Epilogue transform (K1 only, bias != null, N == N6): N-tile 1 (slot b)
// multiplies by 1/sqrt(F); N-tile 4 (slot i) applies sigmoid. This moves
// those ops off the scan's serial critical path.
// ---------------------------------------------------------------------------
#define ASTRIDE 40
#define TILE_E (128 * ASTRIDE)
#define TILE_B (TILE_E * 2)
#define STAGE_B (4 * TILE_B)
#define GEMM_SMEM (2 * STAGE_B)

__device__ __forceinline__ void ldm_x4(uint32_t (&r)[4], const __nv_bfloat16* p) {
    uint32_t addr = (uint32_t)__cvta_generic_to_shared(p);
    asm volatile("ldmatrix.sync.aligned.m8n8.x4.shared.b16 {%0,%1,%2,%3}, [%4];"
                 : "=r"(r[0]), "=r"(r[1]), "=r"(r[2]), "=r"(r[3]) : "r"(addr));
}

__device__ __forceinline__ void mma_bf16(float* d, const uint32_t* a,
                                         uint32_t b0, uint32_t b1) {
    asm volatile(
        "mma.sync.aligned.m16n8k16.row.col.f32.bf16.bf16.f32 "
        "{%0,%1,%2,%3}, {%4,%5,%6,%7}, {%8,%9}, {%0,%1,%2,%3};"
        : "+f"(d[0]), "+f"(d[1]), "+f"(d[2]), "+f"(d[3])
        : "r"(a[0]), "r"(a[1]), "r"(a[2]), "r"(a[3]), "r"(b0), "r"(b1));
}

__device__ __forceinline__ float epi_op(float v, int mode) {
    if (mode == 1) return v * INV_SQRT_F;
    if (mode == 2) return 1.0f / (1.0f + __expf(-v));
    return v;
}

__global__ void __launch_bounds__(256, 2)
bf16_gemm_async(const __nv_bfloat16* __restrict__ Ah,
                const __nv_bfloat16* __restrict__ Al,
                const __nv_bfloat16* __restrict__ Bh,
                const __nv_bfloat16* __restrict__ Bl,
                const float* __restrict__ bias, float* __restrict__ C,
                int M, int N, int K)
{
    extern __shared__ __align__(16) __nv_bfloat16 smd[];

    const int tid = threadIdx.x;
    const int wid = tid >> 5;
    const int lane = tid & 31;
    const int grp = lane >> 2;
    const int tig = lane & 3;

    const int bm = blockIdx.y * 128;
    const int bn = blockIdx.x * 128;
    const int warp_m = (wid >> 1) * 32;
    const int warp_n = (wid & 1) * 64;

    float acc[2][8][4];
#pragma unroll
    for (int mt = 0; mt < 2; mt++)
#pragma unroll
        for (int nt = 0; nt < 8; nt++)
#pragma unroll
            for (int q = 0; q < 4; q++) acc[mt][nt][q] = 0.0f;

    const int lrow = tid >> 1;
    const int cb = (tid & 1) * 2;

    const __nv_bfloat16* gsrc[4];
    gsrc[0] = Ah + (size_t)(bm + lrow) * K;
    gsrc[1] = Al + (size_t)(bm + lrow) * K;
    gsrc[2] = Bh + (size_t)(bn + lrow) * K;
    gsrc[3] = Bl + (size_t)(bn + lrow) * K;

    const uint32_t smem_base = (uint32_t)__cvta_generic_to_shared(smd);
    const uint32_t dst0 = smem_base + (uint32_t)(lrow * ASTRIDE * 2 + cb * 16);

    const int a_e0 = (warp_m + (lane & 15)) * ASTRIDE + ((lane >> 4) & 1) * 8;
    const int b_e0 = (warp_n + (lane & 7) + ((lane >> 4) & 1) * 8) * ASTRIDE
                   + ((lane >> 3) & 1) * 8;

#define ISSUE_STAGE(stg, kk) do {                                          \
    uint32_t _d = dst0 + (uint32_t)(stg) * STAGE_B;                        \
    _Pragma("unroll")                                                      \
    for (int _m = 0; _m < 4; _m++) {                                       \
        cp16(_d + 0,  gsrc[_m] + (kk) + (cb + 0) * 8);                     \
        cp16(_d + 16, gsrc[_m] + (kk) + (cb + 1) * 8);                     \
        _d += TILE_B;                                                      \
    }                                                                      \
    asm volatile("cp.async.commit_group;");                                \
} while (0)

    const int niter = K >> 5;
    ISSUE_STAGE(0, 0);

    for (int i = 0; i < niter; i++) {
        if (i + 1 < niter) {
            ISSUE_STAGE((i + 1) & 1, (i + 1) * 32);
            asm volatile("cp.async.wait_group 1;");
        } else {
            asm volatile("cp.async.wait_group 0;");
        }
        __syncthreads();

        const __nv_bfloat16* sAh = smd + (size_t)((i & 1) * 4 + 0) * TILE_E;
        const __nv_bfloat16* sAl = smd + (size_t)((i & 1) * 4 + 1) * TILE_E;
        const __nv_bfloat16* sBh = smd + (size_t)((i & 1) * 4 + 2) * TILE_E;
        const __nv_bfloat16* sBl = smd + (size_t)((i & 1) * 4 + 3) * TILE_E;

#pragma unroll
        for (int ks = 0; ks < 2; ks++) {
            uint32_t afh[2][4], afl[2][4];
#pragma unroll
            for (int mt = 0; mt < 2; mt++) {
                int e = a_e0 + mt * 16 * ASTRIDE + ks * 16;
                ldm_x4(afh[mt], sAh + e);
                ldm_x4(afl[mt], sAl + e);
            }
#pragma unroll
            for (int ntp = 0; ntp < 4; ntp++) {
                uint32_t bh[4], bl[4];
                int e = b_e0 + ntp * 16 * ASTRIDE + ks * 16;
                ldm_x4(bh, sBh + e);
                ldm_x4(bl, sBl + e);
#pragma unroll
                for (int mt = 0; mt < 2; mt++) {
                    mma_bf16(acc[mt][2 * ntp],     afh[mt], bh[0], bh[1]);
                    mma_bf16(acc[mt][2 * ntp],     afh[mt], bl[0], bl[1]);
                    mma_bf16(acc[mt][2 * ntp],     afl[mt], bh[0], bh[1]);
                    mma_bf16(acc[mt][2 * ntp + 1], afh[mt], bh[2], bh[3]);
                    mma_bf16(acc[mt][2 * ntp + 1], afh[mt], bl[2], bl[3]);
                    mma_bf16(acc[mt][2 * ntp + 1], afl[mt], bh[2], bh[3]);
                }
            }
        }
        __syncthreads();
    }
#undef ISSUE_STAGE

    // epilogue transform mode: only for K1 (bias != null, N == N6)
    int mode = 0;
    if (bias != nullptr && N == N6) {
        if (bn == 1 * F_DIM) mode = 1;        // slot b: scale by 1/sqrt(F)
        else if (bn == 4 * F_DIM) mode = 2;   // slot i: sigmoid
    }

#pragma unroll
    for (int mt = 0; mt < 2; mt++) {
        int r0 = bm + warp_m + mt * 16 + grp;
#pragma unroll
        for (int nt = 0; nt < 8; nt++) {
            int col = bn + warp_n + nt * 8 + 2 * tig;
            float b0 = 0.f, b1 = 0.f;
            if (bias != nullptr) { b0 = bias[col]; b1 = bias[col + 1]; }
            float2 v0 = make_float2(epi_op(acc[mt][nt][0] + b0, mode),
                                    epi_op(acc[mt][nt][1] + b1, mode));
            float2 v1 = make_float2(epi_op(acc[mt][nt][2] + b0, mode),
                                    epi_op(acc[mt][nt][3] + b1, mode));
            *(float2*)(C + (size_t)r0 * N + col) = v0;
            *(float2*)(C + (size_t)(r0 + 8) * N + col) = v1;
        }
    }
}

// ---------------------------------------------------------------------------
// K2: sequential scan with SMEM chunk pipeline.
// Grid (G_GRP, B_DIM), 32 threads per CTA. Lane l owns columns [4l, 4l+4).
// Slot b already scaled by 1/sqrt(F); slot i already sigmoided (GEMM epi).
// 4-way warp reduction uses 10 shfls (fold rows into lane groups).
// Slot layout (floats): a[0..127], b'[128..255], d[256..383], g[384..511],
//                       c[512..515], s[516..519], pad[520..527]
// ---------------------------------------------------------------------------
__global__ void __launch_bounds__(32)
scan_kernel(const float* __restrict__ P, const float* __restrict__ state_in,
            float* __restrict__ opart, float* __restrict__ state_out)
{
    extern __shared__ __align__(16) float sm[];

    const int g = blockIdx.x;
    const int b = blockIdx.y;
    const int l = threadIdx.x;
    const int rowbase = g * R_ROWS;

    const uint32_t smb = (uint32_t)__cvta_generic_to_shared(sm);

#define ISSUE_CHUNK(cc, bi) do {                                              \
    const int _t0 = (cc) * CHUNK;                                             \
    _Pragma("unroll 4")                                                       \
    for (int _s = 0; _s < CHUNK; _s++) {                                      \
        const float* _src = P + (size_t)((size_t)(_t0 + _s) * B_DIM + b) * N6;\
        uint32_t _dst = smb + (uint32_t)(((bi) * BUF_F + _s * SLOT_F) * 4);   \
        cp16(_dst + (uint32_t)(l * 16),          _src + 0 * F_DIM + l * 4);   \
        cp16(_dst + (uint32_t)(512 + l * 16),    _src + 1 * F_DIM + l * 4);   \
        cp16(_dst + (uint32_t)(1024 + l * 16),   _src + 3 * F_DIM + l * 4);   \
        cp16(_dst + (uint32_t)(1536 + l * 16),   _src + 4 * F_DIM + l * 4);   \
        if (l == 0) cp16(_dst + 2048, _src + 2 * F_DIM + rowbase);            \
        if (l == 1) cp16(_dst + 2064, _src + 5 * F_DIM + rowbase);            \
    }                                                                         \
    asm volatile("cp.async.commit_group;");                                   \
} while (0)

    // initial state
    float4 st[R_ROWS];
    {
        const float* sb = state_in + ((size_t)b * F_DIM + rowbase) * F_DIM + 4 * l;
#pragma unroll
        for (int r = 0; r < R_ROWS; r++)
            st[r] = *(const float4*)(sb + r * F_DIM);
    }

    ISSUE_CHUNK(0, 0);
    ISSUE_CHUNK(1, 1);

    const bool hi16 = (l & 16) != 0;
    const bool hi8 = (l & 8) != 0;

    const int NCHUNK = T_DIM / CHUNK;   // 256
#pragma unroll 1
    for (int cc = 0; cc < NCHUNK; cc++) {
        asm volatile("cp.async.wait_group 1;");
        __syncwarp();

        const int bi = cc & 1;
        const float* buf = sm + (size_t)bi * BUF_F;

#pragma unroll 4
        for (int s = 0; s < CHUNK; s++) {
            const int t = cc * CHUNK + s;
            const float* sp = buf + s * SLOT_F;

            float4 a  = *(const float4*)(sp + 4 * l);
            float4 bb = *(const float4*)(sp + 128 + 4 * l);   // pre-scaled
            float4 dd = *(const float4*)(sp + 256 + 4 * l);
            float4 gg = *(const float4*)(sp + 384 + 4 * l);   // pre-sigmoided

            // per-lane partial dots
            float p[R_ROWS];
#pragma unroll
            for (int r = 0; r < R_ROWS; r++) {
                float m01 = fmaf(st[r].y, a.y, st[r].x * a.x);
                float m23 = fmaf(st[r].w, a.w, st[r].z * a.z);
                p[r] = m01 + m23;
            }

            // 10-shfl 4-way allsum:
            // stage 1 (xor16): fold row pairs across half-warps
            float sA = hi16 ? p[0] : p[2];
            float sB = hi16 ? p[1] : p[3];
            float rA = __shfl_xor_sync(0xffffffffu, sA, 16);
            float rB = __shfl_xor_sync(0xffffffffu, sB, 16);
            float q0 = (hi16 ? p[2] : p[0]) + rA;   // r0 (lo) / r2 (hi)
            float q1 = (hi16 ? p[3] : p[1]) + rB;   // r1 (lo) / r3 (hi)
            // stage 2 (xor8): fold q pair across bit-3 groups
            float sC = hi8 ? q0 : q1;
            float rC = __shfl_xor_sync(0xffffffffu, sC, 8);
            float w = (hi8 ? q1 : q0) + rC;
            // stages 3-5: butterfly within 8-lane groups
            w += __shfl_xor_sync(0xffffffffu, w, 4);
            w += __shfl_xor_sync(0xffffffffu, w, 2);
            w += __shfl_xor_sync(0xffffffffu, w, 1);
            // broadcast v0..v3 from group leaders
            float v[R_ROWS];
            v[0] = __shfl_sync(0xffffffffu, w, 0);
            v[1] = __shfl_sync(0xffffffffu, w, 8);
            v[2] = __shfl_sync(0xffffffffu, w, 16);
            v[3] = __shfl_sync(0xffffffffu, w, 24);

            float cc4[R_ROWS], ss4[R_ROWS];
#pragma unroll
            for (int r = 0; r < R_ROWS; r++) {
                cc4[r] = sp[512 + r];
                ss4[r] = sp[516 + r];
            }

            // st = st*g + v*b' + c*d
#pragma unroll
            for (int r = 0; r < R_ROWS; r++) {
                const float cr = cc4[r];
                st[r].x = fmaf(st[r].x, gg.x, fmaf(v[r], bb.x, cr * dd.x));
                st[r].y = fmaf(st[r].y, gg.y, fmaf(v[r], bb.y, cr * dd.y));
                st[r].z = fmaf(st[r].z, gg.z, fmaf(v[r], bb.z, cr * dd.z));
                st[r].w = fmaf(st[r].w, gg.w, fmaf(v[r], bb.w, cr * dd.w));
            }

            // partial output over owned rows
            float4 po = make_float4(0.f, 0.f, 0.f, 0.f);
#pragma unroll
            for (int r = 0; r < R_ROWS; r++) {
                const float sr = ss4[r];
                po.x = fmaf(sr, st[r].x, po.x);
                po.y = fmaf(sr, st[r].y, po.y);
                po.z = fmaf(sr, st[r].z, po.z);
                po.w = fmaf(sr, st[r].w, po.w);
            }
            float* ob = opart +
                ((size_t)((size_t)t * B_DIM + b) * G_GRP + g) * F_DIM + 4 * l;
            *(float4*)ob = po;
        }

        __syncwarp();
        if (cc + 2 < NCHUNK) ISSUE_CHUNK(cc + 2, bi);
    }
#undef ISSUE_CHUNK

    float* so = state_out + ((size_t)b * F_DIM + rowbase) * F_DIM + 4 * l;
#pragma unroll
    for (int r = 0; r < R_ROWS; r++)
        *(float4*)(so + r * F_DIM) = st[r];
}

// ---------------------------------------------------------------------------
// K3: reduce partial outputs over G, emitting bf16 hi/lo for K4
// ---------------------------------------------------------------------------
__global__ void reduce_opart_kernel(const float* __restrict__ opart)
{
    const int F4 = F_DIM / 4;
    size_t idx = (size_t)blockIdx.x * blockDim.x + threadIdx.x;
    size_t total = (size_t)M_DIM * F4;
    if (idx >= total) return;
    size_t row = idx / F4;
    int f4 = (int)(idx % F4);
    const float4* src = (const float4*)opart + row * (size_t)(G_GRP * F4) + f4;
    float4 acc = make_float4(0.f, 0.f, 0.f, 0.f);
#pragma unroll
    for (int gg = 0; gg < G_GRP; gg++) {
        float4 xv = src[(size_t)gg * F4];
        acc.x += xv.x; acc.y += xv.y; acc.z += xv.z; acc.w += xv.w;
    }
    __nv_bfloat16 h0, l0, h1, l1, h2, l2, h3, l3;
    split1(acc.x, h0, l0); split1(acc.y, h1, l1);
    split1(acc.z, h2, l2); split1(acc.w, h3, l3);
    uint2 ph, pl;
    ph.x = (uint32_t)__bfloat16_as_ushort(h0) | ((uint32_t)__bfloat16_as_ushort(h1) << 16);
    ph.y = (uint32_t)__bfloat16_as_ushort(h2) | ((uint32_t)__bfloat16_as_ushort(h3) << 16);
    pl.x = (uint32_t)__bfloat16_as_ushort(l0) | ((uint32_t)__bfloat16_as_ushort(l1) << 16);
    pl.y = (uint32_t)__bfloat16_as_ushort(l2) | ((uint32_t)__bfloat16_as_ushort(l3) << 16);
    ((uint2*)d_oh)[idx] = ph;
    ((uint2*)d_ol)[idx] = pl;
}

// ---------------------------------------------------------------------------
// launch
// ---------------------------------------------------------------------------
extern "C" void kernel_launch(void* const* d_in, const int* in_sizes, int n_in,
                              void* d_out, int out_size)
{
    const float* x     = (const float*)d_in[0];
    const float* state = (const float*)d_in[1];
    const float* A_w = (const float*)d_in[2];
    const float* A_b = (const float*)d_in[3];
    const float* B_w = (const float*)d_in[4];
    const float* B_b = (const float*)d_in[5];
    const float* C_w = (const float*)d_in[6];
    const float* C_b = (const float*)d_in[7];
    const float* D_w = (const float*)d_in[8];
    const float* D_b = (const float*)d_in[9];
    const float* I_w = (const float*)d_in[10];
    const float* I_b = (const float*)d_in[11];
    const float* S_w = (const float*)d_in[12];
    const float* S_b = (const float*)d_in[13];
    const float* O_w = (const float*)d_in[14];

    float* out = (float*)d_out;

    float *b6, *P, *opart, *stfb;
    __nv_bfloat16 *xh, *xl, *W6h, *W6l, *Owh, *Owl, *oh, *ol;
    cudaGetSymbolAddress((void**)&b6, d_b6);
    cudaGetSymbolAddress((void**)&P, d_P);
    cudaGetSymbolAddress((void**)&opart, d_opart);
    cudaGetSymbolAddress((void**)&stfb, d_stfb);
    cudaGetSymbolAddress((void**)&xh, d_xh);
    cudaGetSymbolAddress((void**)&xl, d_xl);
    cudaGetSymbolAddress((void**)&W6h, d_W6h);
    cudaGetSymbolAddress((void**)&W6l, d_W6l);
    cudaGetSymbolAddress((void**)&Owh, d_Owh);
    cudaGetSymbolAddress((void**)&Owl, d_Owl);
    cudaGetSymbolAddress((void**)&oh, d_oh);
    cudaGetSymbolAddress((void**)&ol, d_ol);

    cudaFuncSetAttribute(bf16_gemm_async,
                         cudaFuncAttributeMaxDynamicSharedMemorySize, GEMM_SMEM);
    cudaFuncSetAttribute(scan_kernel,
                         cudaFuncAttributeMaxDynamicSharedMemorySize, SCAN_SMEM);

    const size_t y_elems = (size_t)M_DIM * C_DIM;
    const size_t st_elems = (size_t)B_DIM * F_DIM * F_DIM;
    float* y = out;
    float* state_out =
        ((size_t)out_size >= y_elems + st_elems) ? (out + y_elems) : stfb;

    // pos 1: pack weights + split x (merged)
    {
        size_t total4 = (size_t)M_DIM * C_DIM / 4;
        pack_split_kernel<<<(unsigned)((total4 + 255) / 256), 256>>>(
            x, A_w, B_w, C_w, D_w, I_w, S_w,
            A_b, B_b, C_b, D_b, I_b, S_b, O_w);
    }

    // pos 2: K1  P = x @ W6^T + b6 (+ b-scale / i-sigmoid epilogue)
    {
        dim3 grid(N6 / 128, M_DIM / 128);
        bf16_gemm_async<<<grid, 256, GEMM_SMEM>>>(xh, xl, W6h, W6l, b6, P,
                                                  M_DIM, N6, C_DIM);
    }

    // pos 3: noop (keeps scan at ncu capture position 4)
    noop_kernel<<<1, 1>>>();

    // pos 4: scan (ncu capture position)
    {
        dim3 grid(G_GRP, B_DIM);
        scan_kernel<<<grid, 32, SCAN_SMEM>>>(P, state, opart, state_out);
    }

    // pos 5: reduce partials -> bf16 hi/lo o
    {
        size_t total = (size_t)M_DIM * (F_DIM / 4);
        reduce_opart_kernel<<<(unsigned)((total + 255) / 256), 256>>>(opart);
    }

    // pos 6: K4  y = o @ O_w^T  (M=32768, N=1024, K=128)
    {
        dim3 grid(C_DIM / 128, M_DIM / 128);
        bf16_gemm_async<<<grid, 256, GEMM_SMEM>>>(oh, ol, Owh, Owl, nullptr, y,
                                                  M_DIM, C_DIM, F_DIM);
    }
}